// round 11
// baseline (speedup 1.0000x reference)
#include <cuda_runtime.h>

#define NN 100000
#define EE 1600000
#define FI 128
#define DD 32
#define GG 1000
#define CC 10
#define BN_EPS 1e-5f

// Scratch (device globals: no allocation allowed).
// NOTE: g_deg is zero at entry to every call: zero-initialized at module load,
// and re-zeroed by k_scan23 at the end of each call (after packing into g_rd).
__device__ __align__(128) float g_p[NN * DD];   // projected features per node
__device__ __align__(128) float g_h[NN * DD];   // layer output (pre-BN)
__device__ float g_stats[5 * 2 * DD];           // per-BN-layer [sum(32), sumsq(32)]
__device__ float g_pooled[GG * DD];             // global_add_pool accumulator
__device__ int g_deg[NN];                       // in-degree (zero at call entry)
__device__ int g_row[NN];                       // CSR row offsets (pre-offset scratch)
__device__ int g_pos[NN];                       // fill cursor
__device__ __align__(8) int2 g_rd[NN];          // packed {row, deg}
__device__ int g_csr[EE];                       // src*DD, grouped by dst
__device__ int g_bsum[128];                     // scan block sums

// ---------------------------------------------------------------------------
// Layer-1 projection + degree histogram + scratch init, fused.
// g_deg is already zero at kernel entry (see note above), so the histogram
// atomics are safe in the same kernel as the projection.
__global__ __launch_bounds__(256) void k_proj1(const float* __restrict__ x,
                                               const float* __restrict__ W,
                                               const int* __restrict__ dst) {
    __shared__ __align__(16) float sW[FI * DD];
    for (int i = threadIdx.x; i < FI * DD; i += 256) sW[i] = W[i];

    int node = blockIdx.x * 256 + threadIdx.x;
    if (node < GG * DD) g_pooled[node] = 0.f;
    if (node < 5 * 2 * DD) g_stats[node] = 0.f;

    // degree histogram: grid-stride over edges
    int nthreads = gridDim.x * 256;
    for (int e = node; e < EE; e += nthreads)
        atomicAdd(&g_deg[__ldg(&dst[e])], 1);

    __syncthreads();
    if (node >= NN) return;

    float acc[DD];
#pragma unroll
    for (int j = 0; j < DD; j++) acc[j] = 0.f;

    const float4* xr = (const float4*)(x + (size_t)node * FI);
#pragma unroll 4
    for (int k4 = 0; k4 < FI / 4; k4++) {
        float4 xv = xr[k4];
#pragma unroll
        for (int t = 0; t < 4; t++) {
            float xs = (t == 0) ? xv.x : (t == 1) ? xv.y : (t == 2) ? xv.z : xv.w;
            const float4* wr = (const float4*)&sW[(k4 * 4 + t) * DD];
#pragma unroll
            for (int j4 = 0; j4 < DD / 4; j4++) {
                float4 w = wr[j4];
                acc[j4 * 4 + 0] += xs * w.x;
                acc[j4 * 4 + 1] += xs * w.y;
                acc[j4 * 4 + 2] += xs * w.z;
                acc[j4 * 4 + 3] += xs * w.w;
            }
        }
    }
    float4* pp = (float4*)&g_p[(size_t)node * DD];
#pragma unroll
    for (int j4 = 0; j4 < 8; j4++)
        pp[j4] = make_float4(acc[j4 * 4], acc[j4 * 4 + 1], acc[j4 * 4 + 2], acc[j4 * 4 + 3]);
}

// ---------------------------------------------------------------------------
__global__ __launch_bounds__(256) void k_scan1() {
    int b = blockIdx.x, t = threadIdx.x;
    int lane = t & 31, w = t >> 5;
    int idx0 = b * 1024 + t * 4;
    int v[4];
#pragma unroll
    for (int u = 0; u < 4; u++) v[u] = (idx0 + u < NN) ? g_deg[idx0 + u] : 0;
    int tsum = v[0] + v[1] + v[2] + v[3];
    int incl = tsum;
#pragma unroll
    for (int d = 1; d < 32; d <<= 1) {
        int o = __shfl_up_sync(0xffffffffu, incl, d);
        if (lane >= d) incl += o;
    }
    __shared__ int wsum[8];
    if (lane == 31) wsum[w] = incl;
    __syncthreads();
    int woff = 0;
    for (int i = 0; i < w; i++) woff += wsum[i];
    int run = woff + incl - tsum;
#pragma unroll
    for (int u = 0; u < 4; u++) {
        if (idx0 + u < NN) g_row[idx0 + u] = run;
        run += v[u];
    }
    if (t == 255) g_bsum[b] = woff + incl;
}

// Merged scan2+scan3: block b covers ids [b*256,(b+1)*256) inside chunk b>>2;
// offset = sum of g_bsum[0..chunk-1]. Packs {row,deg} into g_rd and re-zeroes
// g_deg for the next call.
__global__ __launch_bounds__(256) void k_scan23() {
    __shared__ int part[8];
    __shared__ int sOff;
    int t = threadIdx.x;
    int lane = t & 31, w = t >> 5;
    int chunk = blockIdx.x >> 2;
    int v = (t < chunk && t < 128) ? g_bsum[t] : 0;
#pragma unroll
    for (int d = 16; d >= 1; d >>= 1) v += __shfl_xor_sync(0xffffffffu, v, d);
    if (lane == 0) part[w] = v;
    __syncthreads();
    if (t == 0) {
        int s = 0;
#pragma unroll
        for (int i = 0; i < 8; i++) s += part[i];
        sOff = s;
    }
    __syncthreads();
    int i = blockIdx.x * 256 + t;
    if (i < NN) {
        int r = g_row[i] + sOff;
        g_pos[i] = r;
        g_rd[i] = make_int2(r, g_deg[i]);
        g_deg[i] = 0;   // restore invariant for next call
    }
}

__global__ __launch_bounds__(256) void k_fill(const int* __restrict__ src,
                                              const int* __restrict__ dst) {
    int e = blockIdx.x * 256 + threadIdx.x;
    if (e < EE) {
        int slot = atomicAdd(&g_pos[dst[e]], 1);
        g_csr[slot] = src[e] * DD;   // premultiplied index
    }
}

// ---------------------------------------------------------------------------
// Layers 2-5 projection with folded BatchNorm:
//   bn(h) = s*h + c;  p = h @ (diag(s)Wa) + c@Wa
__global__ __launch_bounds__(256) void k_proj(int stats_layer,
                                              const float* __restrict__ gamma,
                                              const float* __restrict__ beta,
                                              const float* __restrict__ Wa) {
    __shared__ float sS[DD], sC[DD], sCB[DD];
    __shared__ __align__(16) float sW[DD * DD];
    const float* st = g_stats + stats_layer * 2 * DD;
    if (threadIdx.x < DD) {
        float m = st[threadIdx.x] * (1.f / NN);
        float v = st[DD + threadIdx.x] * (1.f / NN) - m * m;
        float s = gamma[threadIdx.x] * rsqrtf(v + BN_EPS);
        sS[threadIdx.x] = s;
        sC[threadIdx.x] = beta[threadIdx.x] - m * s;
    }
    __syncthreads();
    for (int i = threadIdx.x; i < DD * DD; i += 256) sW[i] = sS[i >> 5] * Wa[i];
    __syncthreads();
    if (threadIdx.x < DD) {
        float c = 0.f;
#pragma unroll
        for (int f = 0; f < DD; f++) c += sC[f] * Wa[f * DD + threadIdx.x];
        sCB[threadIdx.x] = c;
    }
    __syncthreads();

    int node = blockIdx.x * 256 + threadIdx.x;
    if (node >= NN) return;

    float hv[DD];
    const float4* hr = (const float4*)&g_h[(size_t)node * DD];
#pragma unroll
    for (int j4 = 0; j4 < 8; j4++) {
        float4 t = hr[j4];
        hv[j4 * 4 + 0] = t.x; hv[j4 * 4 + 1] = t.y;
        hv[j4 * 4 + 2] = t.z; hv[j4 * 4 + 3] = t.w;
    }
    float acc[DD];
#pragma unroll
    for (int j = 0; j < DD; j++) acc[j] = sCB[j];
#pragma unroll 4
    for (int k = 0; k < DD; k++) {
        float hk = hv[k];
        const float4* wr = (const float4*)&sW[k * DD];
#pragma unroll
        for (int j4 = 0; j4 < 8; j4++) {
            float4 w = wr[j4];
            acc[j4 * 4 + 0] += hk * w.x;
            acc[j4 * 4 + 1] += hk * w.y;
            acc[j4 * 4 + 2] += hk * w.z;
            acc[j4 * 4 + 3] += hk * w.w;
        }
    }
    float4* pp = (float4*)&g_p[(size_t)node * DD];
#pragma unroll
    for (int j4 = 0; j4 < 8; j4++)
        pp[j4] = make_float4(acc[j4 * 4], acc[j4 * 4 + 1], acc[j4 * 4 + 2], acc[j4 * 4 + 3]);
}

// ---------------------------------------------------------------------------
// Fused gather + MLP + stats. One warp per node.
// Lane layout: sub = lane>>3 (edge subgroup 0..3), quad = lane&7 (float4 chunk).
// Gather: each lane loads float4 -> one warp-load covers 4 edges (512B).
// MLP matvec: t staged in per-warp smem; broadcast LDS.128 reads against a
// register-resident Wb column.
__global__ __launch_bounds__(256) void k_gma(const float* __restrict__ ba,
                                             const float* __restrict__ Wb,
                                             const float* __restrict__ bb,
                                             int stats_layer) {
    __shared__ __align__(16) float sT[8][DD];
    __shared__ float sba4[DD], sS[DD], sQ[DD];
    int lane = threadIdx.x & 31;
    int w = threadIdx.x >> 5;

    float wb[DD];   // column `lane` of Wb
#pragma unroll
    for (int k = 0; k < DD; k++) wb[k] = Wb[k * DD + lane];
    float bbl = bb[lane];

    if (threadIdx.x < DD) {
        sba4[threadIdx.x] = ba[threadIdx.x];
        sS[threadIdx.x] = 0.f;
        sQ[threadIdx.x] = 0.f;
    }
    __syncthreads();

    int sub = lane >> 3;
    int quad = lane & 7;
    const unsigned FULL = 0xffffffffu;

    int warpsTotal = gridDim.x * 8;
    float ls = 0.f, lq = 0.f;

    for (int n = blockIdx.x * 8 + w; n < NN; n += warpsTotal) {
        int2 rd = g_rd[n];
        int base = rd.x, cnt = rd.y;
        float4 a4 = make_float4(0.f, 0.f, 0.f, 0.f);
        int i = 0;
        for (; i + 16 <= cnt; i += 16) {
            int s0 = g_csr[base + i + sub];
            int s1 = g_csr[base + i + 4 + sub];
            int s2 = g_csr[base + i + 8 + sub];
            int s3 = g_csr[base + i + 12 + sub];
            float4 v0 = *(const float4*)&g_p[s0 + quad * 4];
            float4 v1 = *(const float4*)&g_p[s1 + quad * 4];
            float4 v2 = *(const float4*)&g_p[s2 + quad * 4];
            float4 v3 = *(const float4*)&g_p[s3 + quad * 4];
            a4.x += (v0.x + v1.x) + (v2.x + v3.x);
            a4.y += (v0.y + v1.y) + (v2.y + v3.y);
            a4.z += (v0.z + v1.z) + (v2.z + v3.z);
            a4.w += (v0.w + v1.w) + (v2.w + v3.w);
        }
        for (; i + 4 <= cnt; i += 4) {
            int s0 = g_csr[base + i + sub];
            float4 v0 = *(const float4*)&g_p[s0 + quad * 4];
            a4.x += v0.x; a4.y += v0.y; a4.z += v0.z; a4.w += v0.w;
        }
        if (i + sub < cnt) {
            int s0 = g_csr[base + i + sub];
            float4 v0 = *(const float4*)&g_p[s0 + quad * 4];
            a4.x += v0.x; a4.y += v0.y; a4.z += v0.z; a4.w += v0.w;
        }
        // reduce across the 4 edge subgroups
        a4.x += __shfl_xor_sync(FULL, a4.x, 8);
        a4.y += __shfl_xor_sync(FULL, a4.y, 8);
        a4.z += __shfl_xor_sync(FULL, a4.z, 8);
        a4.w += __shfl_xor_sync(FULL, a4.w, 8);
        a4.x += __shfl_xor_sync(FULL, a4.x, 16);
        a4.y += __shfl_xor_sync(FULL, a4.y, 16);
        a4.z += __shfl_xor_sync(FULL, a4.z, 16);
        a4.w += __shfl_xor_sync(FULL, a4.w, 16);

        // self term + bias + relu
        float4 self = *(const float4*)&g_p[n * DD + quad * 4];
        const float4 b4 = *(const float4*)&sba4[quad * 4];
        float4 t4;
        t4.x = fmaxf(a4.x + self.x + b4.x, 0.f);
        t4.y = fmaxf(a4.y + self.y + b4.y, 0.f);
        t4.z = fmaxf(a4.z + self.z + b4.z, 0.f);
        t4.w = fmaxf(a4.w + self.w + b4.w, 0.f);

        __syncwarp();
        if (lane < 8) *(float4*)&sT[w][lane * 4] = t4;
        __syncwarp();

        float hv = bbl;
#pragma unroll
        for (int k4 = 0; k4 < 8; k4++) {
            float4 tv = *(const float4*)&sT[w][k4 * 4];
            hv = fmaf(tv.x, wb[k4 * 4 + 0], hv);
            hv = fmaf(tv.y, wb[k4 * 4 + 1], hv);
            hv = fmaf(tv.z, wb[k4 * 4 + 2], hv);
            hv = fmaf(tv.w, wb[k4 * 4 + 3], hv);
        }
        hv = fmaxf(hv, 0.f);
        g_h[(size_t)n * DD + lane] = hv;
        ls += hv;
        lq += hv * hv;
    }

    atomicAdd(&sS[lane], ls);
    atomicAdd(&sQ[lane], lq);
    __syncthreads();
    if (w == 0) {
        float* st = g_stats + stats_layer * 2 * DD;
        atomicAdd(&st[lane], sS[lane]);
        atomicAdd(&st[DD + lane], sQ[lane]);
    }
}

// ---------------------------------------------------------------------------
// Segmented global add pool (batch is sorted)
__global__ __launch_bounds__(256) void k_pool(const int* __restrict__ batch,
                                              const float* __restrict__ gamma,
                                              const float* __restrict__ beta) {
    __shared__ float sS[DD], sC[DD];
    const float* st = g_stats + 4 * 2 * DD;
    if (threadIdx.x < DD) {
        float m = st[threadIdx.x] * (1.f / NN);
        float v = st[DD + threadIdx.x] * (1.f / NN) - m * m;
        float s = gamma[threadIdx.x] * rsqrtf(v + BN_EPS);
        sS[threadIdx.x] = s;
        sC[threadIdx.x] = beta[threadIdx.x] - m * s;
    }
    __syncthreads();

    int lane = threadIdx.x & 31;
    int w = threadIdx.x >> 5;
    int wid = blockIdx.x * 8 + w;
    int n0 = wid * 64;
    if (n0 >= NN) return;
    int n1 = min(n0 + 64, NN);

    float s = sS[lane], c = sC[lane];
    int curg = __ldg(&batch[n0]);
    float acc = 0.f;
    for (int n = n0; n < n1; n++) {
        int g = __ldg(&batch[n]);
        if (g != curg) {
            atomicAdd(&g_pooled[curg * DD + lane], acc);
            acc = 0.f;
            curg = g;
        }
        acc = fmaf(s, g_h[(size_t)n * DD + lane], acc + c);
    }
    atomicAdd(&g_pooled[curg * DD + lane], acc);
}

// ---------------------------------------------------------------------------
// Head: relu(pooled@fc1+b1) @ fc2 + b2, log_softmax. One thread per graph.
__global__ __launch_bounds__(256) void k_head(const float* __restrict__ fc1w,
                                              const float* __restrict__ fc1b,
                                              const float* __restrict__ fc2w,
                                              const float* __restrict__ fc2b,
                                              float* __restrict__ out) {
    __shared__ float sW1[DD * DD], sW2[DD * CC], sb1[DD], sb2[CC];
    for (int i = threadIdx.x; i < DD * DD; i += 256) sW1[i] = fc1w[i];
    for (int i = threadIdx.x; i < DD * CC; i += 256) sW2[i] = fc2w[i];
    if (threadIdx.x < DD) sb1[threadIdx.x] = fc1b[threadIdx.x];
    if (threadIdx.x < CC) sb2[threadIdx.x] = fc2b[threadIdx.x];
    __syncthreads();

    int g = blockIdx.x * 256 + threadIdx.x;
    if (g >= GG) return;

    float pv[DD];
    const float4* pr = (const float4*)&g_pooled[g * DD];
#pragma unroll
    for (int j4 = 0; j4 < 8; j4++) {
        float4 t = pr[j4];
        pv[j4 * 4 + 0] = t.x; pv[j4 * 4 + 1] = t.y;
        pv[j4 * 4 + 2] = t.z; pv[j4 * 4 + 3] = t.w;
    }
    float u[DD];
#pragma unroll
    for (int j = 0; j < DD; j++) u[j] = sb1[j];
#pragma unroll 4
    for (int k = 0; k < DD; k++) {
        float pk = pv[k];
#pragma unroll
        for (int j = 0; j < DD; j++) u[j] += pk * sW1[k * DD + j];
    }
#pragma unroll
    for (int j = 0; j < DD; j++) u[j] = fmaxf(u[j], 0.f);

    float lg[CC];
#pragma unroll
    for (int c = 0; c < CC; c++) lg[c] = sb2[c];
#pragma unroll 4
    for (int j = 0; j < DD; j++) {
        float uj = u[j];
#pragma unroll
        for (int c = 0; c < CC; c++) lg[c] += uj * sW2[j * CC + c];
    }
    float mx = lg[0];
#pragma unroll
    for (int c = 1; c < CC; c++) mx = fmaxf(mx, lg[c]);
    float se = 0.f;
#pragma unroll
    for (int c = 0; c < CC; c++) se += expf(lg[c] - mx);
    float lse = mx + logf(se);
#pragma unroll
    for (int c = 0; c < CC; c++) out[g * CC + c] = lg[c] - lse;
}

// ---------------------------------------------------------------------------
extern "C" void kernel_launch(void* const* d_in, const int* in_sizes, int n_in,
                              void* d_out, int out_size) {
    const float* x     = (const float*)d_in[0];
    const int*   ei    = (const int*)d_in[1];
    const int*   batch = (const int*)d_in[2];
    const float* W1a   = (const float*)d_in[3];
    const float* b1a   = (const float*)d_in[4];
    const float* W1b   = (const float*)d_in[5];
    const float* b1b   = (const float*)d_in[6];
    const float* Wa    = (const float*)d_in[7];
    const float* ba    = (const float*)d_in[8];
    const float* Wb    = (const float*)d_in[9];
    const float* bb    = (const float*)d_in[10];
    const float* gamma = (const float*)d_in[11];
    const float* beta  = (const float*)d_in[12];
    const float* fc1w  = (const float*)d_in[13];
    const float* fc1b  = (const float*)d_in[14];
    const float* fc2w  = (const float*)d_in[15];
    const float* fc2b  = (const float*)d_in[16];
    float* out = (float*)d_out;

    const int* src = ei;        // row 0
    const int* dst = ei + EE;   // row 1

    const int NB = (NN + 255) / 256;          // 391
    const int EB = EE / 256;                  // 6250
    const int SCAN_BLK = (NN + 1023) / 1024;  // 98
    const int GMA_BLK = 1480;
    const int PB = ((NN + 63) / 64 + 7) / 8;

    // Layer-1 projection + degree histogram + scratch init (fused)
    k_proj1<<<NB, 256>>>(x, W1a, dst);

    // CSR build
    k_scan1<<<SCAN_BLK, 256>>>();
    k_scan23<<<NB, 256>>>();
    k_fill<<<EB, 256>>>(src, dst);

    // Layer 1 gather+MLP+stats
    k_gma<<<GMA_BLK, 256>>>(b1a, W1b, b1b, 0);

    // Layers 2-5 (BN folded into projection)
    for (int i = 0; i < 4; i++) {
        k_proj<<<NB, 256>>>(i, gamma + i * DD, beta + i * DD, Wa + i * DD * DD);
        k_gma<<<GMA_BLK, 256>>>(ba + i * DD, Wb + i * DD * DD, bb + i * DD, i + 1);
    }

    // Pool (applies BN layer 5) + head
    k_pool<<<PB, 256>>>(batch, gamma + 4 * DD, beta + 4 * DD);
    k_head<<<(GG + 255) / 256, 256>>>(fc1w, fc1b, fc2w, fc2b, out);
}

// round 13
// speedup vs baseline: 1.0101x; 1.0101x over previous
#include <cuda_runtime.h>

#define NN 100000
#define EE 1600000
#define FI 128
#define DD 32
#define GG 1000
#define CC 10
#define BN_EPS 1e-5f

// Scratch (device globals: no allocation allowed)
__device__ __align__(128) float g_p[NN * DD];   // projected features per node
__device__ __align__(128) float g_h[NN * DD];   // layer output (pre-BN)
__device__ float g_stats[5 * 2 * DD];           // per-BN-layer [sum(32), sumsq(32)]
__device__ float g_pooled[GG * DD];             // global_add_pool accumulator
__device__ int g_deg[NN];                       // in-degree
__device__ int g_row[NN];                       // CSR row offsets (pre-offset scratch)
__device__ int g_pos[NN];                       // fill cursor
__device__ __align__(8) int2 g_rd[NN];          // packed {row, deg}
__device__ int g_csr[EE];                       // src*DD, grouped by dst
__device__ int g_bsum[128];                     // scan block sums

// ---------------------------------------------------------------------------
// Layer-1 projection: p = x @ W1a  (N x 128 @ 128 x 32). Also inits scratch.
__global__ __launch_bounds__(256) void k_proj1(const float* __restrict__ x,
                                               const float* __restrict__ W) {
    __shared__ __align__(16) float sW[FI * DD];
    for (int i = threadIdx.x; i < FI * DD; i += 256) sW[i] = W[i];

    int node = blockIdx.x * 256 + threadIdx.x;
    if (node < NN) g_deg[node] = 0;
    if (node < GG * DD) g_pooled[node] = 0.f;
    if (node < 5 * 2 * DD) g_stats[node] = 0.f;
    __syncthreads();

    if (node >= NN) return;

    float acc[DD];
#pragma unroll
    for (int j = 0; j < DD; j++) acc[j] = 0.f;

    const float4* xr = (const float4*)(x + (size_t)node * FI);
#pragma unroll 4
    for (int k4 = 0; k4 < FI / 4; k4++) {
        float4 xv = xr[k4];
#pragma unroll
        for (int t = 0; t < 4; t++) {
            float xs = (t == 0) ? xv.x : (t == 1) ? xv.y : (t == 2) ? xv.z : xv.w;
            const float4* wr = (const float4*)&sW[(k4 * 4 + t) * DD];
#pragma unroll
            for (int j4 = 0; j4 < DD / 4; j4++) {
                float4 w = wr[j4];
                acc[j4 * 4 + 0] += xs * w.x;
                acc[j4 * 4 + 1] += xs * w.y;
                acc[j4 * 4 + 2] += xs * w.z;
                acc[j4 * 4 + 3] += xs * w.w;
            }
        }
    }
    float4* pp = (float4*)&g_p[(size_t)node * DD];
#pragma unroll
    for (int j4 = 0; j4 < 8; j4++)
        pp[j4] = make_float4(acc[j4 * 4], acc[j4 * 4 + 1], acc[j4 * 4 + 2], acc[j4 * 4 + 3]);
}

// ---------------------------------------------------------------------------
// CSR build
__global__ __launch_bounds__(256) void k_hist(const int* __restrict__ dst) {
    int e = blockIdx.x * 256 + threadIdx.x;
    if (e < EE) atomicAdd(&g_deg[dst[e]], 1);
}

__global__ __launch_bounds__(256) void k_scan1() {
    int b = blockIdx.x, t = threadIdx.x;
    int lane = t & 31, w = t >> 5;
    int idx0 = b * 1024 + t * 4;
    int v[4];
#pragma unroll
    for (int u = 0; u < 4; u++) v[u] = (idx0 + u < NN) ? g_deg[idx0 + u] : 0;
    int tsum = v[0] + v[1] + v[2] + v[3];
    int incl = tsum;
#pragma unroll
    for (int d = 1; d < 32; d <<= 1) {
        int o = __shfl_up_sync(0xffffffffu, incl, d);
        if (lane >= d) incl += o;
    }
    __shared__ int wsum[8];
    if (lane == 31) wsum[w] = incl;
    __syncthreads();
    int woff = 0;
    for (int i = 0; i < w; i++) woff += wsum[i];
    int run = woff + incl - tsum;
#pragma unroll
    for (int u = 0; u < 4; u++) {
        if (idx0 + u < NN) g_row[idx0 + u] = run;
        run += v[u];
    }
    if (t == 255) g_bsum[b] = woff + incl;
}

// Merged scan2+scan3: block b covers ids [b*256,(b+1)*256) inside chunk b>>2;
// offset = sum of g_bsum[0..chunk-1]. Packs {row,deg} into g_rd.
__global__ __launch_bounds__(256) void k_scan23() {
    __shared__ int part[8];
    __shared__ int sOff;
    int t = threadIdx.x;
    int lane = t & 31, w = t >> 5;
    int chunk = blockIdx.x >> 2;
    int v = (t < chunk && t < 128) ? g_bsum[t] : 0;
#pragma unroll
    for (int d = 16; d >= 1; d >>= 1) v += __shfl_xor_sync(0xffffffffu, v, d);
    if (lane == 0) part[w] = v;
    __syncthreads();
    if (t == 0) {
        int s = 0;
#pragma unroll
        for (int i = 0; i < 8; i++) s += part[i];
        sOff = s;
    }
    __syncthreads();
    int i = blockIdx.x * 256 + t;
    if (i < NN) {
        int r = g_row[i] + sOff;
        g_pos[i] = r;
        g_rd[i] = make_int2(r, g_deg[i]);
    }
}

__global__ __launch_bounds__(256) void k_fill(const int* __restrict__ src,
                                              const int* __restrict__ dst) {
    int e = blockIdx.x * 256 + threadIdx.x;
    if (e < EE) {
        int slot = atomicAdd(&g_pos[dst[e]], 1);
        g_csr[slot] = src[e] * DD;   // premultiplied index
    }
}

// ---------------------------------------------------------------------------
// Layers 2-5 projection with folded BatchNorm:
//   bn(h) = s*h + c;  p = h @ (diag(s)Wa) + c@Wa
__global__ __launch_bounds__(256) void k_proj(int stats_layer,
                                              const float* __restrict__ gamma,
                                              const float* __restrict__ beta,
                                              const float* __restrict__ Wa) {
    __shared__ float sS[DD], sC[DD], sCB[DD];
    __shared__ __align__(16) float sW[DD * DD];
    const float* st = g_stats + stats_layer * 2 * DD;
    if (threadIdx.x < DD) {
        float m = st[threadIdx.x] * (1.f / NN);
        float v = st[DD + threadIdx.x] * (1.f / NN) - m * m;
        float s = gamma[threadIdx.x] * rsqrtf(v + BN_EPS);
        sS[threadIdx.x] = s;
        sC[threadIdx.x] = beta[threadIdx.x] - m * s;
    }
    __syncthreads();
    for (int i = threadIdx.x; i < DD * DD; i += 256) sW[i] = sS[i >> 5] * Wa[i];
    __syncthreads();
    if (threadIdx.x < DD) {
        float c = 0.f;
#pragma unroll
        for (int f = 0; f < DD; f++) c += sC[f] * Wa[f * DD + threadIdx.x];
        sCB[threadIdx.x] = c;
    }
    __syncthreads();

    int node = blockIdx.x * 256 + threadIdx.x;
    if (node >= NN) return;

    float hv[DD];
    const float4* hr = (const float4*)&g_h[(size_t)node * DD];
#pragma unroll
    for (int j4 = 0; j4 < 8; j4++) {
        float4 t = hr[j4];
        hv[j4 * 4 + 0] = t.x; hv[j4 * 4 + 1] = t.y;
        hv[j4 * 4 + 2] = t.z; hv[j4 * 4 + 3] = t.w;
    }
    float acc[DD];
#pragma unroll
    for (int j = 0; j < DD; j++) acc[j] = sCB[j];
#pragma unroll 4
    for (int k = 0; k < DD; k++) {
        float hk = hv[k];
        const float4* wr = (const float4*)&sW[k * DD];
#pragma unroll
        for (int j4 = 0; j4 < 8; j4++) {
            float4 w = wr[j4];
            acc[j4 * 4 + 0] += hk * w.x;
            acc[j4 * 4 + 1] += hk * w.y;
            acc[j4 * 4 + 2] += hk * w.z;
            acc[j4 * 4 + 3] += hk * w.w;
        }
    }
    float4* pp = (float4*)&g_p[(size_t)node * DD];
#pragma unroll
    for (int j4 = 0; j4 < 8; j4++)
        pp[j4] = make_float4(acc[j4 * 4], acc[j4 * 4 + 1], acc[j4 * 4 + 2], acc[j4 * 4 + 3]);
}

// ---------------------------------------------------------------------------
// Fused gather + MLP + stats. One warp per node.
// Lane layout: sub = lane>>3 (edge subgroup 0..3), quad = lane&7 (float4 chunk).
// Gather: each lane loads float4 -> one warp-load covers 4 edges (512B).
// MLP matvec: t staged in per-warp smem; broadcast LDS.128 against a
// register-resident Wb column. Next node's {row,deg} prefetched each iter.
__global__ __launch_bounds__(256) void k_gma(const float* __restrict__ ba,
                                             const float* __restrict__ Wb,
                                             const float* __restrict__ bb,
                                             int stats_layer) {
    __shared__ __align__(16) float sT[8][DD];
    __shared__ float sba4[DD], sS[DD], sQ[DD];
    int lane = threadIdx.x & 31;
    int w = threadIdx.x >> 5;

    float wb[DD];   // column `lane` of Wb
#pragma unroll
    for (int k = 0; k < DD; k++) wb[k] = Wb[k * DD + lane];
    float bbl = bb[lane];

    if (threadIdx.x < DD) {
        sba4[threadIdx.x] = ba[threadIdx.x];
        sS[threadIdx.x] = 0.f;
        sQ[threadIdx.x] = 0.f;
    }
    __syncthreads();

    int sub = lane >> 3;
    int quad = lane & 7;
    const unsigned FULL = 0xffffffffu;

    int warpsTotal = gridDim.x * 8;
    float ls = 0.f, lq = 0.f;

    int n0 = blockIdx.x * 8 + w;
    int2 rd = (n0 < NN) ? g_rd[n0] : make_int2(0, 0);

    for (int n = n0; n < NN; n += warpsTotal) {
        int base = rd.x, cnt = rd.y;
        int nn = n + warpsTotal;
        if (nn < NN) rd = g_rd[nn];   // prefetch next node's descriptor

        float4 a4 = make_float4(0.f, 0.f, 0.f, 0.f);
        int i = 0;
        for (; i + 16 <= cnt; i += 16) {
            int s0 = g_csr[base + i + sub];
            int s1 = g_csr[base + i + 4 + sub];
            int s2 = g_csr[base + i + 8 + sub];
            int s3 = g_csr[base + i + 12 + sub];
            float4 v0 = *(const float4*)&g_p[s0 + quad * 4];
            float4 v1 = *(const float4*)&g_p[s1 + quad * 4];
            float4 v2 = *(const float4*)&g_p[s2 + quad * 4];
            float4 v3 = *(const float4*)&g_p[s3 + quad * 4];
            a4.x += (v0.x + v1.x) + (v2.x + v3.x);
            a4.y += (v0.y + v1.y) + (v2.y + v3.y);
            a4.z += (v0.z + v1.z) + (v2.z + v3.z);
            a4.w += (v0.w + v1.w) + (v2.w + v3.w);
        }
        for (; i + 4 <= cnt; i += 4) {
            int s0 = g_csr[base + i + sub];
            float4 v0 = *(const float4*)&g_p[s0 + quad * 4];
            a4.x += v0.x; a4.y += v0.y; a4.z += v0.z; a4.w += v0.w;
        }
        if (i + sub < cnt) {
            int s0 = g_csr[base + i + sub];
            float4 v0 = *(const float4*)&g_p[s0 + quad * 4];
            a4.x += v0.x; a4.y += v0.y; a4.z += v0.z; a4.w += v0.w;
        }
        // reduce across the 4 edge subgroups
        a4.x += __shfl_xor_sync(FULL, a4.x, 8);
        a4.y += __shfl_xor_sync(FULL, a4.y, 8);
        a4.z += __shfl_xor_sync(FULL, a4.z, 8);
        a4.w += __shfl_xor_sync(FULL, a4.w, 8);
        a4.x += __shfl_xor_sync(FULL, a4.x, 16);
        a4.y += __shfl_xor_sync(FULL, a4.y, 16);
        a4.z += __shfl_xor_sync(FULL, a4.z, 16);
        a4.w += __shfl_xor_sync(FULL, a4.w, 16);

        // self term + bias + relu
        float4 self = *(const float4*)&g_p[n * DD + quad * 4];
        const float4 b4 = *(const float4*)&sba4[quad * 4];
        float4 t4;
        t4.x = fmaxf(a4.x + self.x + b4.x, 0.f);
        t4.y = fmaxf(a4.y + self.y + b4.y, 0.f);
        t4.z = fmaxf(a4.z + self.z + b4.z, 0.f);
        t4.w = fmaxf(a4.w + self.w + b4.w, 0.f);

        __syncwarp();
        if (lane < 8) *(float4*)&sT[w][lane * 4] = t4;
        __syncwarp();

        float hv = bbl;
#pragma unroll
        for (int k4 = 0; k4 < 8; k4++) {
            float4 tv = *(const float4*)&sT[w][k4 * 4];
            hv = fmaf(tv.x, wb[k4 * 4 + 0], hv);
            hv = fmaf(tv.y, wb[k4 * 4 + 1], hv);
            hv = fmaf(tv.z, wb[k4 * 4 + 2], hv);
            hv = fmaf(tv.w, wb[k4 * 4 + 3], hv);
        }
        hv = fmaxf(hv, 0.f);
        g_h[(size_t)n * DD + lane] = hv;
        ls += hv;
        lq += hv * hv;
    }

    atomicAdd(&sS[lane], ls);
    atomicAdd(&sQ[lane], lq);
    __syncthreads();
    if (w == 0) {
        float* st = g_stats + stats_layer * 2 * DD;
        atomicAdd(&st[lane], sS[lane]);
        atomicAdd(&st[DD + lane], sQ[lane]);
    }
}

// ---------------------------------------------------------------------------
// Segmented global add pool (batch is sorted)
__global__ __launch_bounds__(256) void k_pool(const int* __restrict__ batch,
                                              const float* __restrict__ gamma,
                                              const float* __restrict__ beta) {
    __shared__ float sS[DD], sC[DD];
    const float* st = g_stats + 4 * 2 * DD;
    if (threadIdx.x < DD) {
        float m = st[threadIdx.x] * (1.f / NN);
        float v = st[DD + threadIdx.x] * (1.f / NN) - m * m;
        float s = gamma[threadIdx.x] * rsqrtf(v + BN_EPS);
        sS[threadIdx.x] = s;
        sC[threadIdx.x] = beta[threadIdx.x] - m * s;
    }
    __syncthreads();

    int lane = threadIdx.x & 31;
    int w = threadIdx.x >> 5;
    int wid = blockIdx.x * 8 + w;
    int n0 = wid * 64;
    if (n0 >= NN) return;
    int n1 = min(n0 + 64, NN);

    float s = sS[lane], c = sC[lane];
    int curg = __ldg(&batch[n0]);
    float acc = 0.f;
    for (int n = n0; n < n1; n++) {
        int g = __ldg(&batch[n]);
        if (g != curg) {
            atomicAdd(&g_pooled[curg * DD + lane], acc);
            acc = 0.f;
            curg = g;
        }
        acc = fmaf(s, g_h[(size_t)n * DD + lane], acc + c);
    }
    atomicAdd(&g_pooled[curg * DD + lane], acc);
}

// ---------------------------------------------------------------------------
// Head: relu(pooled@fc1+b1) @ fc2 + b2, log_softmax. One thread per graph.
__global__ __launch_bounds__(256) void k_head(const float* __restrict__ fc1w,
                                              const float* __restrict__ fc1b,
                                              const float* __restrict__ fc2w,
                                              const float* __restrict__ fc2b,
                                              float* __restrict__ out) {
    __shared__ float sW1[DD * DD], sW2[DD * CC], sb1[DD], sb2[CC];
    for (int i = threadIdx.x; i < DD * DD; i += 256) sW1[i] = fc1w[i];
    for (int i = threadIdx.x; i < DD * CC; i += 256) sW2[i] = fc2w[i];
    if (threadIdx.x < DD) sb1[threadIdx.x] = fc1b[threadIdx.x];
    if (threadIdx.x < CC) sb2[threadIdx.x] = fc2b[threadIdx.x];
    __syncthreads();

    int g = blockIdx.x * 256 + threadIdx.x;
    if (g >= GG) return;

    float pv[DD];
    const float4* pr = (const float4*)&g_pooled[g * DD];
#pragma unroll
    for (int j4 = 0; j4 < 8; j4++) {
        float4 t = pr[j4];
        pv[j4 * 4 + 0] = t.x; pv[j4 * 4 + 1] = t.y;
        pv[j4 * 4 + 2] = t.z; pv[j4 * 4 + 3] = t.w;
    }
    float u[DD];
#pragma unroll
    for (int j = 0; j < DD; j++) u[j] = sb1[j];
#pragma unroll 4
    for (int k = 0; k < DD; k++) {
        float pk = pv[k];
#pragma unroll
        for (int j = 0; j < DD; j++) u[j] += pk * sW1[k * DD + j];
    }
#pragma unroll
    for (int j = 0; j < DD; j++) u[j] = fmaxf(u[j], 0.f);

    float lg[CC];
#pragma unroll
    for (int c = 0; c < CC; c++) lg[c] = sb2[c];
#pragma unroll 4
    for (int j = 0; j < DD; j++) {
        float uj = u[j];
#pragma unroll
        for (int c = 0; c < CC; c++) lg[c] += uj * sW2[j * CC + c];
    }
    float mx = lg[0];
#pragma unroll
    for (int c = 1; c < CC; c++) mx = fmaxf(mx, lg[c]);
    float se = 0.f;
#pragma unroll
    for (int c = 0; c < CC; c++) se += expf(lg[c] - mx);
    float lse = mx + logf(se);
#pragma unroll
    for (int c = 0; c < CC; c++) out[g * CC + c] = lg[c] - lse;
}

// ---------------------------------------------------------------------------
extern "C" void kernel_launch(void* const* d_in, const int* in_sizes, int n_in,
                              void* d_out, int out_size) {
    const float* x     = (const float*)d_in[0];
    const int*   ei    = (const int*)d_in[1];
    const int*   batch = (const int*)d_in[2];
    const float* W1a   = (const float*)d_in[3];
    const float* b1a   = (const float*)d_in[4];
    const float* W1b   = (const float*)d_in[5];
    const float* b1b   = (const float*)d_in[6];
    const float* Wa    = (const float*)d_in[7];
    const float* ba    = (const float*)d_in[8];
    const float* Wb    = (const float*)d_in[9];
    const float* bb    = (const float*)d_in[10];
    const float* gamma = (const float*)d_in[11];
    const float* beta  = (const float*)d_in[12];
    const float* fc1w  = (const float*)d_in[13];
    const float* fc1b  = (const float*)d_in[14];
    const float* fc2w  = (const float*)d_in[15];
    const float* fc2b  = (const float*)d_in[16];
    float* out = (float*)d_out;

    const int* src = ei;        // row 0
    const int* dst = ei + EE;   // row 1

    const int NB = (NN + 255) / 256;          // 391
    const int EB = EE / 256;                  // 6250
    const int SCAN_BLK = (NN + 1023) / 1024;  // 98
    const int GMA_BLK = 1480;
    const int PB = ((NN + 63) / 64 + 7) / 8;

    // Layer-1 projection + scratch init (independent of CSR build)
    k_proj1<<<NB, 256>>>(x, W1a);

    // CSR build (dst-grouped edge list)
    k_hist<<<EB, 256>>>(dst);
    k_scan1<<<SCAN_BLK, 256>>>();
    k_scan23<<<NB, 256>>>();
    k_fill<<<EB, 256>>>(src, dst);

    // Layer 1 gather+MLP+stats
    k_gma<<<GMA_BLK, 256>>>(b1a, W1b, b1b, 0);

    // Layers 2-5 (BN folded into projection)
    for (int i = 0; i < 4; i++) {
        k_proj<<<NB, 256>>>(i, gamma + i * DD, beta + i * DD, Wa + i * DD * DD);
        k_gma<<<GMA_BLK, 256>>>(ba + i * DD, Wb + i * DD * DD, bb + i * DD, i + 1);
    }

    // Pool (applies BN layer 5) + head
    k_pool<<<PB, 256>>>(batch, gamma + 4 * DD, beta + 4 * DD);
    k_head<<<(GG + 255) / 256, 256>>>(fc1w, fc1b, fc2w, fc2b, out);
}

// round 15
// speedup vs baseline: 1.0940x; 1.0831x over previous
#include <cuda_runtime.h>

#define NN 100000
#define EE 1600000
#define FI 128
#define DD 32
#define GG 1000
#define CC 10
#define BN_EPS 1e-5f

// Scratch (device globals: no allocation allowed).
// INVARIANT: g_deg is zero at entry to every kernel_launch call — zeroed at
// module load, and re-zeroed by k_scan23 within each call (after packing the
// degree into g_rd). This lets k_hist run first with no init kernel.
__device__ __align__(128) float g_p[NN * DD];   // projected features per node
__device__ __align__(128) float g_h[NN * DD];   // layer output (pre-BN)
__device__ float g_stats[5 * 2 * DD];           // per-BN-layer [sum(32), sumsq(32)]
__device__ float g_pooled[GG * DD];             // global_add_pool accumulator
__device__ int g_deg[NN];                       // in-degree (zero at call entry)
__device__ int g_row[NN];                       // CSR row offsets (pre-offset scratch)
__device__ int g_pos[NN];                       // fill cursor
__device__ __align__(8) int2 g_rd[NN];          // packed {row, deg}
__device__ int g_csr[EE];                       // src ids grouped by dst
__device__ int g_bsum[128];                     // scan block sums

// ---------------------------------------------------------------------------
// CSR degree histogram (g_deg zero by invariant above)
__global__ __launch_bounds__(256) void k_hist(const int* __restrict__ dst) {
    int e = blockIdx.x * 256 + threadIdx.x;
    if (e < EE) atomicAdd(&g_deg[dst[e]], 1);
}

__global__ __launch_bounds__(256) void k_scan1() {
    int b = blockIdx.x, t = threadIdx.x;
    int lane = t & 31, w = t >> 5;
    int idx0 = b * 1024 + t * 4;
    int v[4];
#pragma unroll
    for (int u = 0; u < 4; u++) v[u] = (idx0 + u < NN) ? g_deg[idx0 + u] : 0;
    int tsum = v[0] + v[1] + v[2] + v[3];
    int incl = tsum;
#pragma unroll
    for (int d = 1; d < 32; d <<= 1) {
        int o = __shfl_up_sync(0xffffffffu, incl, d);
        if (lane >= d) incl += o;
    }
    __shared__ int wsum[8];
    if (lane == 31) wsum[w] = incl;
    __syncthreads();
    int woff = 0;
    for (int i = 0; i < w; i++) woff += wsum[i];
    int run = woff + incl - tsum;
#pragma unroll
    for (int u = 0; u < 4; u++) {
        if (idx0 + u < NN) g_row[idx0 + u] = run;
        run += v[u];
    }
    if (t == 255) g_bsum[b] = woff + incl;
}

// Merged scan2+scan3: block b covers ids [b*256,(b+1)*256) inside chunk b>>2;
// offset = sum of g_bsum[0..chunk-1]. Packs {row,deg} into g_rd, re-zeroes
// g_deg (restores invariant), and inits g_pooled/g_stats.
__global__ __launch_bounds__(256) void k_scan23() {
    __shared__ int part[8];
    __shared__ int sOff;
    int t = threadIdx.x;
    int lane = t & 31, w = t >> 5;
    int chunk = blockIdx.x >> 2;
    int v = (t < chunk && t < 128) ? g_bsum[t] : 0;
#pragma unroll
    for (int d = 16; d >= 1; d >>= 1) v += __shfl_xor_sync(0xffffffffu, v, d);
    if (lane == 0) part[w] = v;
    __syncthreads();
    if (t == 0) {
        int s = 0;
#pragma unroll
        for (int i = 0; i < 8; i++) s += part[i];
        sOff = s;
    }
    __syncthreads();
    int i = blockIdx.x * 256 + t;
    if (i < NN) {
        int r = g_row[i] + sOff;
        g_pos[i] = r;
        g_rd[i] = make_int2(r, g_deg[i]);
        g_deg[i] = 0;   // restore invariant for next call
    }
    if (i < GG * DD) g_pooled[i] = 0.f;
    if (i < 5 * 2 * DD) g_stats[i] = 0.f;
}

// ---------------------------------------------------------------------------
// Heterogeneous kernel: blocks [0, EB) do the CSR fill (atomic/L2-bound);
// blocks [EB, EB+NB) do the layer-1 projection p = x @ W1a (FMA-bound).
// The two halves are independent and overlap their complementary bottlenecks.
#define EB 6250
__global__ __launch_bounds__(256) void k_fillproj(const int* __restrict__ src,
                                                  const int* __restrict__ dst,
                                                  const float* __restrict__ x,
                                                  const float* __restrict__ W) {
    __shared__ __align__(16) float sW[FI * DD];

    if (blockIdx.x < EB) {
        int e = blockIdx.x * 256 + threadIdx.x;
        if (e < EE) {
            int slot = atomicAdd(&g_pos[dst[e]], 1);
            g_csr[slot] = src[e];
        }
        return;
    }

    // projection half
    for (int i = threadIdx.x; i < FI * DD; i += 256) sW[i] = W[i];
    __syncthreads();

    int node = (blockIdx.x - EB) * 256 + threadIdx.x;
    if (node >= NN) return;

    float acc[DD];
#pragma unroll
    for (int j = 0; j < DD; j++) acc[j] = 0.f;

    const float4* xr = (const float4*)(x + (size_t)node * FI);
#pragma unroll 4
    for (int k4 = 0; k4 < FI / 4; k4++) {
        float4 xv = xr[k4];
#pragma unroll
        for (int t = 0; t < 4; t++) {
            float xs = (t == 0) ? xv.x : (t == 1) ? xv.y : (t == 2) ? xv.z : xv.w;
            const float4* wr = (const float4*)&sW[(k4 * 4 + t) * DD];
#pragma unroll
            for (int j4 = 0; j4 < DD / 4; j4++) {
                float4 w = wr[j4];
                acc[j4 * 4 + 0] += xs * w.x;
                acc[j4 * 4 + 1] += xs * w.y;
                acc[j4 * 4 + 2] += xs * w.z;
                acc[j4 * 4 + 3] += xs * w.w;
            }
        }
    }
    float4* pp = (float4*)&g_p[(size_t)node * DD];
#pragma unroll
    for (int j4 = 0; j4 < 8; j4++)
        pp[j4] = make_float4(acc[j4 * 4], acc[j4 * 4 + 1], acc[j4 * 4 + 2], acc[j4 * 4 + 3]);
}

// ---------------------------------------------------------------------------
// Layers 2-5 projection with folded BatchNorm:
//   bn(h) = s*h + c;  p = h @ (diag(s)Wa) + c@Wa
__global__ __launch_bounds__(256) void k_proj(int stats_layer,
                                              const float* __restrict__ gamma,
                                              const float* __restrict__ beta,
                                              const float* __restrict__ Wa) {
    __shared__ float sS[DD], sC[DD], sCB[DD];
    __shared__ __align__(16) float sW[DD * DD];
    const float* st = g_stats + stats_layer * 2 * DD;
    if (threadIdx.x < DD) {
        float m = st[threadIdx.x] * (1.f / NN);
        float v = st[DD + threadIdx.x] * (1.f / NN) - m * m;
        float s = gamma[threadIdx.x] * rsqrtf(v + BN_EPS);
        sS[threadIdx.x] = s;
        sC[threadIdx.x] = beta[threadIdx.x] - m * s;
    }
    __syncthreads();
    for (int i = threadIdx.x; i < DD * DD; i += 256) sW[i] = sS[i >> 5] * Wa[i];
    __syncthreads();
    if (threadIdx.x < DD) {
        float c = 0.f;
#pragma unroll
        for (int f = 0; f < DD; f++) c += sC[f] * Wa[f * DD + threadIdx.x];
        sCB[threadIdx.x] = c;
    }
    __syncthreads();

    int node = blockIdx.x * 256 + threadIdx.x;
    if (node >= NN) return;

    float hv[DD];
    const float4* hr = (const float4*)&g_h[(size_t)node * DD];
#pragma unroll
    for (int j4 = 0; j4 < 8; j4++) {
        float4 t = hr[j4];
        hv[j4 * 4 + 0] = t.x; hv[j4 * 4 + 1] = t.y;
        hv[j4 * 4 + 2] = t.z; hv[j4 * 4 + 3] = t.w;
    }
    float acc[DD];
#pragma unroll
    for (int j = 0; j < DD; j++) acc[j] = sCB[j];
#pragma unroll 4
    for (int k = 0; k < DD; k++) {
        float hk = hv[k];
        const float4* wr = (const float4*)&sW[k * DD];
#pragma unroll
        for (int j4 = 0; j4 < 8; j4++) {
            float4 w = wr[j4];
            acc[j4 * 4 + 0] += hk * w.x;
            acc[j4 * 4 + 1] += hk * w.y;
            acc[j4 * 4 + 2] += hk * w.z;
            acc[j4 * 4 + 3] += hk * w.w;
        }
    }
    float4* pp = (float4*)&g_p[(size_t)node * DD];
#pragma unroll
    for (int j4 = 0; j4 < 8; j4++)
        pp[j4] = make_float4(acc[j4 * 4], acc[j4 * 4 + 1], acc[j4 * 4 + 2], acc[j4 * 4 + 3]);
}

// ---------------------------------------------------------------------------
// Fused gather + MLP + stats (R6 hot path; only change: {row,deg} via one
// LDG.64 from g_rd). One warp per node; sub = lane>>3, quad = lane&7.
__global__ __launch_bounds__(256) void k_gma(const float* __restrict__ ba,
                                             const float* __restrict__ Wb,
                                             const float* __restrict__ bb,
                                             int stats_layer) {
    __shared__ __align__(16) float sT[8][DD];
    __shared__ float sba4[DD], sS[DD], sQ[DD];
    int lane = threadIdx.x & 31;
    int w = threadIdx.x >> 5;

    float wb[DD];   // column `lane` of Wb
#pragma unroll
    for (int k = 0; k < DD; k++) wb[k] = Wb[k * DD + lane];
    float bbl = bb[lane];

    if (threadIdx.x < DD) {
        sba4[threadIdx.x] = ba[threadIdx.x];
        sS[threadIdx.x] = 0.f;
        sQ[threadIdx.x] = 0.f;
    }
    __syncthreads();

    int sub = lane >> 3;
    int quad = lane & 7;
    const unsigned FULL = 0xffffffffu;

    int warpsTotal = gridDim.x * 8;
    float ls = 0.f, lq = 0.f;

    for (int n = blockIdx.x * 8 + w; n < NN; n += warpsTotal) {
        int2 rd = g_rd[n];
        int base = rd.x, cnt = rd.y;
        float4 a4 = make_float4(0.f, 0.f, 0.f, 0.f);
        int i = 0;
        for (; i + 16 <= cnt; i += 16) {
            int s0 = g_csr[base + i + sub];
            int s1 = g_csr[base + i + 4 + sub];
            int s2 = g_csr[base + i + 8 + sub];
            int s3 = g_csr[base + i + 12 + sub];
            float4 v0 = *(const float4*)&g_p[(size_t)s0 * DD + quad * 4];
            float4 v1 = *(const float4*)&g_p[(size_t)s1 * DD + quad * 4];
            float4 v2 = *(const float4*)&g_p[(size_t)s2 * DD + quad * 4];
            float4 v3 = *(const float4*)&g_p[(size_t)s3 * DD + quad * 4];
            a4.x += (v0.x + v1.x) + (v2.x + v3.x);
            a4.y += (v0.y + v1.y) + (v2.y + v3.y);
            a4.z += (v0.z + v1.z) + (v2.z + v3.z);
            a4.w += (v0.w + v1.w) + (v2.w + v3.w);
        }
        for (; i + 4 <= cnt; i += 4) {
            int s0 = g_csr[base + i + sub];
            float4 v0 = *(const float4*)&g_p[(size_t)s0 * DD + quad * 4];
            a4.x += v0.x; a4.y += v0.y; a4.z += v0.z; a4.w += v0.w;
        }
        if (i + sub < cnt) {
            int s0 = g_csr[base + i + sub];
            float4 v0 = *(const float4*)&g_p[(size_t)s0 * DD + quad * 4];
            a4.x += v0.x; a4.y += v0.y; a4.z += v0.z; a4.w += v0.w;
        }
        // reduce across the 4 edge subgroups
        a4.x += __shfl_xor_sync(FULL, a4.x, 8);
        a4.y += __shfl_xor_sync(FULL, a4.y, 8);
        a4.z += __shfl_xor_sync(FULL, a4.z, 8);
        a4.w += __shfl_xor_sync(FULL, a4.w, 8);
        a4.x += __shfl_xor_sync(FULL, a4.x, 16);
        a4.y += __shfl_xor_sync(FULL, a4.y, 16);
        a4.z += __shfl_xor_sync(FULL, a4.z, 16);
        a4.w += __shfl_xor_sync(FULL, a4.w, 16);

        // self term + bias + relu
        float4 self = *(const float4*)&g_p[(size_t)n * DD + quad * 4];
        const float4 b4 = *(const float4*)&sba4[quad * 4];
        float4 t4;
        t4.x = fmaxf(a4.x + self.x + b4.x, 0.f);
        t4.y = fmaxf(a4.y + self.y + b4.y, 0.f);
        t4.z = fmaxf(a4.z + self.z + b4.z, 0.f);
        t4.w = fmaxf(a4.w + self.w + b4.w, 0.f);

        __syncwarp();
        if (lane < 8) *(float4*)&sT[w][lane * 4] = t4;
        __syncwarp();

        float hv = bbl;
#pragma unroll
        for (int k4 = 0; k4 < 8; k4++) {
            float4 tv = *(const float4*)&sT[w][k4 * 4];
            hv = fmaf(tv.x, wb[k4 * 4 + 0], hv);
            hv = fmaf(tv.y, wb[k4 * 4 + 1], hv);
            hv = fmaf(tv.z, wb[k4 * 4 + 2], hv);
            hv = fmaf(tv.w, wb[k4 * 4 + 3], hv);
        }
        hv = fmaxf(hv, 0.f);
        g_h[(size_t)n * DD + lane] = hv;
        ls += hv;
        lq += hv * hv;
    }

    atomicAdd(&sS[lane], ls);
    atomicAdd(&sQ[lane], lq);
    __syncthreads();
    if (w == 0) {
        float* st = g_stats + stats_layer * 2 * DD;
        atomicAdd(&st[lane], sS[lane]);
        atomicAdd(&st[DD + lane], sQ[lane]);
    }
}

// ---------------------------------------------------------------------------
// Segmented global add pool (batch is sorted)
__global__ __launch_bounds__(256) void k_pool(const int* __restrict__ batch,
                                              const float* __restrict__ gamma,
                                              const float* __restrict__ beta) {
    __shared__ float sS[DD], sC[DD];
    const float* st = g_stats + 4 * 2 * DD;
    if (threadIdx.x < DD) {
        float m = st[threadIdx.x] * (1.f / NN);
        float v = st[DD + threadIdx.x] * (1.f / NN) - m * m;
        float s = gamma[threadIdx.x] * rsqrtf(v + BN_EPS);
        sS[threadIdx.x] = s;
        sC[threadIdx.x] = beta[threadIdx.x] - m * s;
    }
    __syncthreads();

    int lane = threadIdx.x & 31;
    int w = threadIdx.x >> 5;
    int wid = blockIdx.x * 8 + w;
    int n0 = wid * 64;
    if (n0 >= NN) return;
    int n1 = min(n0 + 64, NN);

    float s = sS[lane], c = sC[lane];
    int curg = __ldg(&batch[n0]);
    float acc = 0.f;
    for (int n = n0; n < n1; n++) {
        int g = __ldg(&batch[n]);
        if (g != curg) {
            atomicAdd(&g_pooled[curg * DD + lane], acc);
            acc = 0.f;
            curg = g;
        }
        acc = fmaf(s, g_h[(size_t)n * DD + lane], acc + c);
    }
    atomicAdd(&g_pooled[curg * DD + lane], acc);
}

// ---------------------------------------------------------------------------
// Head: relu(pooled@fc1+b1) @ fc2 + b2, log_softmax. One thread per graph.
__global__ __launch_bounds__(256) void k_head(const float* __restrict__ fc1w,
                                              const float* __restrict__ fc1b,
                                              const float* __restrict__ fc2w,
                                              const float* __restrict__ fc2b,
                                              float* __restrict__ out) {
    __shared__ float sW1[DD * DD], sW2[DD * CC], sb1[DD], sb2[CC];
    for (int i = threadIdx.x; i < DD * DD; i += 256) sW1[i] = fc1w[i];
    for (int i = threadIdx.x; i < DD * CC; i += 256) sW2[i] = fc2w[i];
    if (threadIdx.x < DD) sb1[threadIdx.x] = fc1b[threadIdx.x];
    if (threadIdx.x < CC) sb2[threadIdx.x] = fc2b[threadIdx.x];
    __syncthreads();

    int g = blockIdx.x * 256 + threadIdx.x;
    if (g >= GG) return;

    float pv[DD];
    const float4* pr = (const float4*)&g_pooled[g * DD];
#pragma unroll
    for (int j4 = 0; j4 < 8; j4++) {
        float4 t = pr[j4];
        pv[j4 * 4 + 0] = t.x; pv[j4 * 4 + 1] = t.y;
        pv[j4 * 4 + 2] = t.z; pv[j4 * 4 + 3] = t.w;
    }
    float u[DD];
#pragma unroll
    for (int j = 0; j < DD; j++) u[j] = sb1[j];
#pragma unroll 4
    for (int k = 0; k < DD; k++) {
        float pk = pv[k];
#pragma unroll
        for (int j = 0; j < DD; j++) u[j] += pk * sW1[k * DD + j];
    }
#pragma unroll
    for (int j = 0; j < DD; j++) u[j] = fmaxf(u[j], 0.f);

    float lg[CC];
#pragma unroll
    for (int c = 0; c < CC; c++) lg[c] = sb2[c];
#pragma unroll 4
    for (int j = 0; j < DD; j++) {
        float uj = u[j];
#pragma unroll
        for (int c = 0; c < CC; c++) lg[c] += uj * sW2[j * CC + c];
    }
    float mx = lg[0];
#pragma unroll
    for (int c = 1; c < CC; c++) mx = fmaxf(mx, lg[c]);
    float se = 0.f;
#pragma unroll
    for (int c = 0; c < CC; c++) se += expf(lg[c] - mx);
    float lse = mx + logf(se);
#pragma unroll
    for (int c = 0; c < CC; c++) out[g * CC + c] = lg[c] - lse;
}

// ---------------------------------------------------------------------------
extern "C" void kernel_launch(void* const* d_in, const int* in_sizes, int n_in,
                              void* d_out, int out_size) {
    const float* x     = (const float*)d_in[0];
    const int*   ei    = (const int*)d_in[1];
    const int*   batch = (const int*)d_in[2];
    const float* W1a   = (const float*)d_in[3];
    const float* b1a   = (const float*)d_in[4];
    const float* W1b   = (const float*)d_in[5];
    const float* b1b   = (const float*)d_in[6];
    const float* Wa    = (const float*)d_in[7];
    const float* ba    = (const float*)d_in[8];
    const float* Wb    = (const float*)d_in[9];
    const float* bb    = (const float*)d_in[10];
    const float* gamma = (const float*)d_in[11];
    const float* beta  = (const float*)d_in[12];
    const float* fc1w  = (const float*)d_in[13];
    const float* fc1b  = (const float*)d_in[14];
    const float* fc2w  = (const float*)d_in[15];
    const float* fc2b  = (const float*)d_in[16];
    float* out = (float*)d_out;

    const int* src = ei;        // row 0
    const int* dst = ei + EE;   // row 1

    const int NB = (NN + 255) / 256;          // 391
    const int SCAN_BLK = (NN + 1023) / 1024;  // 98
    const int GMA_BLK = 1480;
    const int PB = ((NN + 63) / 64 + 7) / 8;

    // CSR build front (g_deg zero by invariant)
    k_hist<<<EB, 256>>>(dst);
    k_scan1<<<SCAN_BLK, 256>>>();
    k_scan23<<<NB, 256>>>();

    // CSR fill overlapped with layer-1 projection
    k_fillproj<<<EB + NB, 256>>>(src, dst, x, W1a);

    // Layer 1 gather+MLP+stats
    k_gma<<<GMA_BLK, 256>>>(b1a, W1b, b1b, 0);

    // Layers 2-5 (BN folded into projection)
    for (int i = 0; i < 4; i++) {
        k_proj<<<NB, 256>>>(i, gamma + i * DD, beta + i * DD, Wa + i * DD * DD);
        k_gma<<<GMA_BLK, 256>>>(ba + i * DD, Wb + i * DD * DD, bb + i * DD, i + 1);
    }

    // Pool (applies BN layer 5) + head
    k_pool<<<PB, 256>>>(batch, gamma + 4 * DD, beta + 4 * DD);
    k_head<<<(GG + 255) / 256, 256>>>(fc1w, fc1b, fc2w, fc2b, out);
}

// round 16
// speedup vs baseline: 1.1176x; 1.0216x over previous
#include <cuda_runtime.h>

#define NN 100000
#define EE 1600000
#define FI 128
#define DD 32
#define GG 1000
#define CC 10
#define BN_EPS 1e-5f
#define CSRMAX (EE + 16 * NN)

// Scratch (device globals: no allocation allowed).
// INVARIANT: g_deg is zero at entry to every kernel_launch call — zeroed at
// module load (.bss), re-zeroed by k_scan23 within each call.
// g_p has one extra row (index NN) that is NEVER written: the zero row that
// CSR padding entries point at (zero from module-load zero-init).
__device__ __align__(128) float g_p[(NN + 1) * DD];
__device__ __align__(128) float g_h[NN * DD];   // layer output (pre-BN)
__device__ float g_stats[5 * 2 * DD];           // per-BN-layer [sum(32), sumsq(32)]
__device__ float g_pooled[GG * DD];             // global_add_pool accumulator
__device__ int g_deg[NN];                       // in-degree (zero at call entry)
__device__ int g_row[NN];                       // padded CSR row offsets (scratch)
__device__ int g_pos[NN];                       // fill cursor
__device__ __align__(8) int2 g_rd[NN];          // packed {row, padded_deg}
__device__ int g_csr[CSRMAX];                   // src ids grouped by dst (padded)
__device__ int g_bsum[128];                     // scan block sums

// ---------------------------------------------------------------------------
// CSR degree histogram (g_deg zero by invariant above)
__global__ __launch_bounds__(256) void k_hist(const int* __restrict__ dst) {
    int e = blockIdx.x * 256 + threadIdx.x;
    if (e < EE) atomicAdd(&g_deg[dst[e]], 1);
}

// Exclusive scan over PADDED degrees (pad to multiple of 16)
__global__ __launch_bounds__(256) void k_scan1() {
    int b = blockIdx.x, t = threadIdx.x;
    int lane = t & 31, w = t >> 5;
    int idx0 = b * 1024 + t * 4;
    int v[4];
#pragma unroll
    for (int u = 0; u < 4; u++)
        v[u] = (idx0 + u < NN) ? ((g_deg[idx0 + u] + 15) & ~15) : 0;
    int tsum = v[0] + v[1] + v[2] + v[3];
    int incl = tsum;
#pragma unroll
    for (int d = 1; d < 32; d <<= 1) {
        int o = __shfl_up_sync(0xffffffffu, incl, d);
        if (lane >= d) incl += o;
    }
    __shared__ int wsum[8];
    if (lane == 31) wsum[w] = incl;
    __syncthreads();
    int woff = 0;
    for (int i = 0; i < w; i++) woff += wsum[i];
    int run = woff + incl - tsum;
#pragma unroll
    for (int u = 0; u < 4; u++) {
        if (idx0 + u < NN) g_row[idx0 + u] = run;
        run += v[u];
    }
    if (t == 255) g_bsum[b] = woff + incl;
}

// Merged scan2+scan3: adds chunk offset, packs {row, padded_deg} into g_rd,
// writes zero-row padding entries into g_csr, re-zeroes g_deg, inits
// g_pooled/g_stats.
__global__ __launch_bounds__(256) void k_scan23() {
    __shared__ int part[8];
    __shared__ int sOff;
    int t = threadIdx.x;
    int lane = t & 31, w = t >> 5;
    int chunk = blockIdx.x >> 2;
    int v = (t < chunk && t < 128) ? g_bsum[t] : 0;
#pragma unroll
    for (int d = 16; d >= 1; d >>= 1) v += __shfl_xor_sync(0xffffffffu, v, d);
    if (lane == 0) part[w] = v;
    __syncthreads();
    if (t == 0) {
        int s = 0;
#pragma unroll
        for (int i = 0; i < 8; i++) s += part[i];
        sOff = s;
    }
    __syncthreads();
    int i = blockIdx.x * 256 + t;
    if (i < NN) {
        int r = g_row[i] + sOff;
        int d = g_deg[i];
        int dp = (d + 15) & ~15;
        g_pos[i] = r;
        g_rd[i] = make_int2(r, dp);
        g_deg[i] = 0;   // restore invariant for next call
        for (int q = r + d; q < r + dp; q++) g_csr[q] = NN;  // zero-row padding
    }
    if (i < GG * DD) g_pooled[i] = 0.f;
    if (i < 5 * 2 * DD) g_stats[i] = 0.f;
}

// CSR fill (real edges; padding already written by k_scan23)
__global__ __launch_bounds__(256) void k_fill(const int* __restrict__ src,
                                              const int* __restrict__ dst) {
    int e = blockIdx.x * 256 + threadIdx.x;
    if (e < EE) {
        int slot = atomicAdd(&g_pos[dst[e]], 1);
        g_csr[slot] = src[e];
    }
}

// ---------------------------------------------------------------------------
// Layer-1 projection: p = x @ W1a  (N x 128 @ 128 x 32)
__global__ __launch_bounds__(256) void k_proj1(const float* __restrict__ x,
                                               const float* __restrict__ W) {
    __shared__ __align__(16) float sW[FI * DD];
    for (int i = threadIdx.x; i < FI * DD; i += 256) sW[i] = W[i];
    __syncthreads();

    int node = blockIdx.x * 256 + threadIdx.x;
    if (node >= NN) return;

    float acc[DD];
#pragma unroll
    for (int j = 0; j < DD; j++) acc[j] = 0.f;

    const float4* xr = (const float4*)(x + (size_t)node * FI);
#pragma unroll 4
    for (int k4 = 0; k4 < FI / 4; k4++) {
        float4 xv = xr[k4];
#pragma unroll
        for (int t = 0; t < 4; t++) {
            float xs = (t == 0) ? xv.x : (t == 1) ? xv.y : (t == 2) ? xv.z : xv.w;
            const float4* wr = (const float4*)&sW[(k4 * 4 + t) * DD];
#pragma unroll
            for (int j4 = 0; j4 < DD / 4; j4++) {
                float4 w = wr[j4];
                acc[j4 * 4 + 0] += xs * w.x;
                acc[j4 * 4 + 1] += xs * w.y;
                acc[j4 * 4 + 2] += xs * w.z;
                acc[j4 * 4 + 3] += xs * w.w;
            }
        }
    }
    float4* pp = (float4*)&g_p[(size_t)node * DD];
#pragma unroll
    for (int j4 = 0; j4 < 8; j4++)
        pp[j4] = make_float4(acc[j4 * 4], acc[j4 * 4 + 1], acc[j4 * 4 + 2], acc[j4 * 4 + 3]);
}

// ---------------------------------------------------------------------------
// Layers 2-5 projection with folded BatchNorm:
//   bn(h) = s*h + c;  p = h @ (diag(s)Wa) + c@Wa
__global__ __launch_bounds__(256) void k_proj(int stats_layer,
                                              const float* __restrict__ gamma,
                                              const float* __restrict__ beta,
                                              const float* __restrict__ Wa) {
    __shared__ float sS[DD], sC[DD], sCB[DD];
    __shared__ __align__(16) float sW[DD * DD];
    const float* st = g_stats + stats_layer * 2 * DD;
    if (threadIdx.x < DD) {
        float m = st[threadIdx.x] * (1.f / NN);
        float v = st[DD + threadIdx.x] * (1.f / NN) - m * m;
        float s = gamma[threadIdx.x] * rsqrtf(v + BN_EPS);
        sS[threadIdx.x] = s;
        sC[threadIdx.x] = beta[threadIdx.x] - m * s;
    }
    __syncthreads();
    for (int i = threadIdx.x; i < DD * DD; i += 256) sW[i] = sS[i >> 5] * Wa[i];
    __syncthreads();
    if (threadIdx.x < DD) {
        float c = 0.f;
#pragma unroll
        for (int f = 0; f < DD; f++) c += sC[f] * Wa[f * DD + threadIdx.x];
        sCB[threadIdx.x] = c;
    }
    __syncthreads();

    int node = blockIdx.x * 256 + threadIdx.x;
    if (node >= NN) return;

    float hv[DD];
    const float4* hr = (const float4*)&g_h[(size_t)node * DD];
#pragma unroll
    for (int j4 = 0; j4 < 8; j4++) {
        float4 t = hr[j4];
        hv[j4 * 4 + 0] = t.x; hv[j4 * 4 + 1] = t.y;
        hv[j4 * 4 + 2] = t.z; hv[j4 * 4 + 3] = t.w;
    }
    float acc[DD];
#pragma unroll
    for (int j = 0; j < DD; j++) acc[j] = sCB[j];
#pragma unroll 4
    for (int k = 0; k < DD; k++) {
        float hk = hv[k];
        const float4* wr = (const float4*)&sW[k * DD];
#pragma unroll
        for (int j4 = 0; j4 < 8; j4++) {
            float4 w = wr[j4];
            acc[j4 * 4 + 0] += hk * w.x;
            acc[j4 * 4 + 1] += hk * w.y;
            acc[j4 * 4 + 2] += hk * w.z;
            acc[j4 * 4 + 3] += hk * w.w;
        }
    }
    float4* pp = (float4*)&g_p[(size_t)node * DD];
#pragma unroll
    for (int j4 = 0; j4 < 8; j4++)
        pp[j4] = make_float4(acc[j4 * 4], acc[j4 * 4 + 1], acc[j4 * 4 + 2], acc[j4 * 4 + 3]);
}

// ---------------------------------------------------------------------------
// Fused gather + MLP + stats. One warp per node; sub = lane>>3, quad = lane&7.
// CSR rows are padded to multiples of 16 with zero-row entries, so the gather
// is ONE uniform loop — no remainder chains.
__global__ __launch_bounds__(256) void k_gma(const float* __restrict__ ba,
                                             const float* __restrict__ Wb,
                                             const float* __restrict__ bb,
                                             int stats_layer) {
    __shared__ __align__(16) float sT[8][DD];
    __shared__ float sba4[DD], sS[DD], sQ[DD];
    int lane = threadIdx.x & 31;
    int w = threadIdx.x >> 5;

    float wb[DD];   // column `lane` of Wb
#pragma unroll
    for (int k = 0; k < DD; k++) wb[k] = Wb[k * DD + lane];
    float bbl = bb[lane];

    if (threadIdx.x < DD) {
        sba4[threadIdx.x] = ba[threadIdx.x];
        sS[threadIdx.x] = 0.f;
        sQ[threadIdx.x] = 0.f;
    }
    __syncthreads();

    int sub = lane >> 3;
    int quad = lane & 7;
    const unsigned FULL = 0xffffffffu;

    int warpsTotal = gridDim.x * 8;
    float ls = 0.f, lq = 0.f;

    for (int n = blockIdx.x * 8 + w; n < NN; n += warpsTotal) {
        int2 rd = g_rd[n];
        int base = rd.x, cnt = rd.y;   // cnt is a multiple of 16
        float4 a4 = make_float4(0.f, 0.f, 0.f, 0.f);
        for (int i = 0; i < cnt; i += 16) {
            int s0 = g_csr[base + i + sub];
            int s1 = g_csr[base + i + 4 + sub];
            int s2 = g_csr[base + i + 8 + sub];
            int s3 = g_csr[base + i + 12 + sub];
            float4 v0 = *(const float4*)&g_p[(size_t)s0 * DD + quad * 4];
            float4 v1 = *(const float4*)&g_p[(size_t)s1 * DD + quad * 4];
            float4 v2 = *(const float4*)&g_p[(size_t)s2 * DD + quad * 4];
            float4 v3 = *(const float4*)&g_p[(size_t)s3 * DD + quad * 4];
            a4.x += (v0.x + v1.x) + (v2.x + v3.x);
            a4.y += (v0.y + v1.y) + (v2.y + v3.y);
            a4.z += (v0.z + v1.z) + (v2.z + v3.z);
            a4.w += (v0.w + v1.w) + (v2.w + v3.w);
        }
        // reduce across the 4 edge subgroups
        a4.x += __shfl_xor_sync(FULL, a4.x, 8);
        a4.y += __shfl_xor_sync(FULL, a4.y, 8);
        a4.z += __shfl_xor_sync(FULL, a4.z, 8);
        a4.w += __shfl_xor_sync(FULL, a4.w, 8);
        a4.x += __shfl_xor_sync(FULL, a4.x, 16);
        a4.y += __shfl_xor_sync(FULL, a4.y, 16);
        a4.z += __shfl_xor_sync(FULL, a4.z, 16);
        a4.w += __shfl_xor_sync(FULL, a4.w, 16);

        // self term + bias + relu
        float4 self = *(const float4*)&g_p[(size_t)n * DD + quad * 4];
        const float4 b4 = *(const float4*)&sba4[quad * 4];
        float4 t4;
        t4.x = fmaxf(a4.x + self.x + b4.x, 0.f);
        t4.y = fmaxf(a4.y + self.y + b4.y, 0.f);
        t4.z = fmaxf(a4.z + self.z + b4.z, 0.f);
        t4.w = fmaxf(a4.w + self.w + b4.w, 0.f);

        __syncwarp();
        if (lane < 8) *(float4*)&sT[w][lane * 4] = t4;
        __syncwarp();

        float hv = bbl;
#pragma unroll
        for (int k4 = 0; k4 < 8; k4++) {
            float4 tv = *(const float4*)&sT[w][k4 * 4];
            hv = fmaf(tv.x, wb[k4 * 4 + 0], hv);
            hv = fmaf(tv.y, wb[k4 * 4 + 1], hv);
            hv = fmaf(tv.z, wb[k4 * 4 + 2], hv);
            hv = fmaf(tv.w, wb[k4 * 4 + 3], hv);
        }
        hv = fmaxf(hv, 0.f);
        g_h[(size_t)n * DD + lane] = hv;
        ls += hv;
        lq += hv * hv;
    }

    atomicAdd(&sS[lane], ls);
    atomicAdd(&sQ[lane], lq);
    __syncthreads();
    if (w == 0) {
        float* st = g_stats + stats_layer * 2 * DD;
        atomicAdd(&st[lane], sS[lane]);
        atomicAdd(&st[DD + lane], sQ[lane]);
    }
}

// ---------------------------------------------------------------------------
// Segmented global add pool (batch is sorted)
__global__ __launch_bounds__(256) void k_pool(const int* __restrict__ batch,
                                              const float* __restrict__ gamma,
                                              const float* __restrict__ beta) {
    __shared__ float sS[DD], sC[DD];
    const float* st = g_stats + 4 * 2 * DD;
    if (threadIdx.x < DD) {
        float m = st[threadIdx.x] * (1.f / NN);
        float v = st[DD + threadIdx.x] * (1.f / NN) - m * m;
        float s = gamma[threadIdx.x] * rsqrtf(v + BN_EPS);
        sS[threadIdx.x] = s;
        sC[threadIdx.x] = beta[threadIdx.x] - m * s;
    }
    __syncthreads();

    int lane = threadIdx.x & 31;
    int w = threadIdx.x >> 5;
    int wid = blockIdx.x * 8 + w;
    int n0 = wid * 64;
    if (n0 >= NN) return;
    int n1 = min(n0 + 64, NN);

    float s = sS[lane], c = sC[lane];
    int curg = __ldg(&batch[n0]);
    float acc = 0.f;
    for (int n = n0; n < n1; n++) {
        int g = __ldg(&batch[n]);
        if (g != curg) {
            atomicAdd(&g_pooled[curg * DD + lane], acc);
            acc = 0.f;
            curg = g;
        }
        acc = fmaf(s, g_h[(size_t)n * DD + lane], acc + c);
    }
    atomicAdd(&g_pooled[curg * DD + lane], acc);
}

// ---------------------------------------------------------------------------
// Head: relu(pooled@fc1+b1) @ fc2 + b2, log_softmax. One thread per graph.
__global__ __launch_bounds__(256) void k_head(const float* __restrict__ fc1w,
                                              const float* __restrict__ fc1b,
                                              const float* __restrict__ fc2w,
                                              const float* __restrict__ fc2b,
                                              float* __restrict__ out) {
    __shared__ float sW1[DD * DD], sW2[DD * CC], sb1[DD], sb2[CC];
    for (int i = threadIdx.x; i < DD * DD; i += 256) sW1[i] = fc1w[i];
    for (int i = threadIdx.x; i < DD * CC; i += 256) sW2[i] = fc2w[i];
    if (threadIdx.x < DD) sb1[threadIdx.x] = fc1b[threadIdx.x];
    if (threadIdx.x < CC) sb2[threadIdx.x] = fc2b[threadIdx.x];
    __syncthreads();

    int g = blockIdx.x * 256 + threadIdx.x;
    if (g >= GG) return;

    float pv[DD];
    const float4* pr = (const float4*)&g_pooled[g * DD];
#pragma unroll
    for (int j4 = 0; j4 < 8; j4++) {
        float4 t = pr[j4];
        pv[j4 * 4 + 0] = t.x; pv[j4 * 4 + 1] = t.y;
        pv[j4 * 4 + 2] = t.z; pv[j4 * 4 + 3] = t.w;
    }
    float u[DD];
#pragma unroll
    for (int j = 0; j < DD; j++) u[j] = sb1[j];
#pragma unroll 4
    for (int k = 0; k < DD; k++) {
        float pk = pv[k];
#pragma unroll
        for (int j = 0; j < DD; j++) u[j] += pk * sW1[k * DD + j];
    }
#pragma unroll
    for (int j = 0; j < DD; j++) u[j] = fmaxf(u[j], 0.f);

    float lg[CC];
#pragma unroll
    for (int c = 0; c < CC; c++) lg[c] = sb2[c];
#pragma unroll 4
    for (int j = 0; j < DD; j++) {
        float uj = u[j];
#pragma unroll
        for (int c = 0; c < CC; c++) lg[c] += uj * sW2[j * CC + c];
    }
    float mx = lg[0];
#pragma unroll
    for (int c = 1; c < CC; c++) mx = fmaxf(mx, lg[c]);
    float se = 0.f;
#pragma unroll
    for (int c = 0; c < CC; c++) se += expf(lg[c] - mx);
    float lse = mx + logf(se);
#pragma unroll
    for (int c = 0; c < CC; c++) out[g * CC + c] = lg[c] - lse;
}

// ---------------------------------------------------------------------------
extern "C" void kernel_launch(void* const* d_in, const int* in_sizes, int n_in,
                              void* d_out, int out_size) {
    const float* x     = (const float*)d_in[0];
    const int*   ei    = (const int*)d_in[1];
    const int*   batch = (const int*)d_in[2];
    const float* W1a   = (const float*)d_in[3];
    const float* b1a   = (const float*)d_in[4];
    const float* W1b   = (const float*)d_in[5];
    const float* b1b   = (const float*)d_in[6];
    const float* Wa    = (const float*)d_in[7];
    const float* ba    = (const float*)d_in[8];
    const float* Wb    = (const float*)d_in[9];
    const float* bb    = (const float*)d_in[10];
    const float* gamma = (const float*)d_in[11];
    const float* beta  = (const float*)d_in[12];
    const float* fc1w  = (const float*)d_in[13];
    const float* fc1b  = (const float*)d_in[14];
    const float* fc2w  = (const float*)d_in[15];
    const float* fc2b  = (const float*)d_in[16];
    float* out = (float*)d_out;

    const int* src = ei;        // row 0
    const int* dst = ei + EE;   // row 1

    const int NB = (NN + 255) / 256;          // 391
    const int EB = EE / 256;                  // 6250
    const int SCAN_BLK = (NN + 1023) / 1024;  // 98
    const int GMA_BLK = 1480;
    const int PB = ((NN + 63) / 64 + 7) / 8;

    // CSR build (padded rows; g_deg zero by invariant)
    k_hist<<<EB, 256>>>(dst);
    k_scan1<<<SCAN_BLK, 256>>>();
    k_scan23<<<NB, 256>>>();
    k_fill<<<EB, 256>>>(src, dst);

    // Layer-1 projection
    k_proj1<<<NB, 256>>>(x, W1a);

    // Layer 1 gather+MLP+stats
    k_gma<<<GMA_BLK, 256>>>(b1a, W1b, b1b, 0);

    // Layers 2-5 (BN folded into projection)
    for (int i = 0; i < 4; i++) {
        k_proj<<<NB, 256>>>(i, gamma + i * DD, beta + i * DD, Wa + i * DD * DD);
        k_gma<<<GMA_BLK, 256>>>(ba + i * DD, Wb + i * DD * DD, bb + i * DD, i + 1);
    }

    // Pool (applies BN layer 5) + head
    k_pool<<<PB, 256>>>(batch, gamma + 4 * DD, beta + 4 * DD);
    k_head<<<(GG + 255) / 256, 256>>>(fc1w, fc1b, fc2w, fc2b, out);
}

// round 17
// speedup vs baseline: 1.1304x; 1.0114x over previous
#include <cuda_runtime.h>
#include <cuda_fp16.h>

#define NN 100000
#define EE 1600000
#define FI 128
#define DD 32
#define GG 1000
#define CC 10
#define BN_EPS 1e-5f
#define CSRMAX (EE + 16 * NN)

// Scratch (device globals: no allocation allowed).
// INVARIANT: g_deg is zero at entry to every kernel_launch call — zeroed at
// module load (.bss), re-zeroed by k_scan23 within each call.
// g_p/g_ph have one extra row (index NN) that is NEVER written: the zero row
// that CSR padding entries point at (zero from module-load zero-init).
__device__ __align__(128) float g_p[(NN + 1) * DD];    // projected feats (fp32)
__device__ __align__(128) __half g_ph[(NN + 1) * DD];  // fp16 copy for gather
__device__ __align__(128) float g_h[NN * DD];   // layer output (pre-BN)
__device__ float g_stats[5 * 2 * DD];           // per-BN-layer [sum(32), sumsq(32)]
__device__ float g_pooled[GG * DD];             // global_add_pool accumulator
__device__ int g_deg[NN];                       // in-degree (zero at call entry)
__device__ int g_row[NN];                       // padded CSR row offsets (scratch)
__device__ int g_pos[NN];                       // fill cursor
__device__ __align__(8) int2 g_rd[NN];          // packed {row, padded_deg}
__device__ int g_csr[CSRMAX];                   // src ids grouped by dst (padded)
__device__ int g_bsum[128];                     // scan block sums

// ---------------------------------------------------------------------------
// CSR degree histogram (g_deg zero by invariant above)
__global__ __launch_bounds__(256) void k_hist(const int* __restrict__ dst) {
    int e = blockIdx.x * 256 + threadIdx.x;
    if (e < EE) atomicAdd(&g_deg[dst[e]], 1);
}

// Exclusive scan over PADDED degrees (pad to multiple of 16)
__global__ __launch_bounds__(256) void k_scan1() {
    int b = blockIdx.x, t = threadIdx.x;
    int lane = t & 31, w = t >> 5;
    int idx0 = b * 1024 + t * 4;
    int v[4];
#pragma unroll
    for (int u = 0; u < 4; u++)
        v[u] = (idx0 + u < NN) ? ((g_deg[idx0 + u] + 15) & ~15) : 0;
    int tsum = v[0] + v[1] + v[2] + v[3];
    int incl = tsum;
#pragma unroll
    for (int d = 1; d < 32; d <<= 1) {
        int o = __shfl_up_sync(0xffffffffu, incl, d);
        if (lane >= d) incl += o;
    }
    __shared__ int wsum[8];
    if (lane == 31) wsum[w] = incl;
    __syncthreads();
    int woff = 0;
    for (int i = 0; i < w; i++) woff += wsum[i];
    int run = woff + incl - tsum;
#pragma unroll
    for (int u = 0; u < 4; u++) {
        if (idx0 + u < NN) g_row[idx0 + u] = run;
        run += v[u];
    }
    if (t == 255) g_bsum[b] = woff + incl;
}

// Merged scan2+scan3: adds chunk offset, packs {row, padded_deg} into g_rd,
// writes zero-row padding entries into g_csr, re-zeroes g_deg, inits
// g_pooled/g_stats.
__global__ __launch_bounds__(256) void k_scan23() {
    __shared__ int part[8];
    __shared__ int sOff;
    int t = threadIdx.x;
    int lane = t & 31, w = t >> 5;
    int chunk = blockIdx.x >> 2;
    int v = (t < chunk && t < 128) ? g_bsum[t] : 0;
#pragma unroll
    for (int d = 16; d >= 1; d >>= 1) v += __shfl_xor_sync(0xffffffffu, v, d);
    if (lane == 0) part[w] = v;
    __syncthreads();
    if (t == 0) {
        int s = 0;
#pragma unroll
        for (int i = 0; i < 8; i++) s += part[i];
        sOff = s;
    }
    __syncthreads();
    int i = blockIdx.x * 256 + t;
    if (i < NN) {
        int r = g_row[i] + sOff;
        int d = g_deg[i];
        int dp = (d + 15) & ~15;
        g_pos[i] = r;
        g_rd[i] = make_int2(r, dp);
        g_deg[i] = 0;   // restore invariant for next call
        for (int q = r + d; q < r + dp; q++) g_csr[q] = NN;  // zero-row padding
    }
    if (i < GG * DD) g_pooled[i] = 0.f;
    if (i < 5 * 2 * DD) g_stats[i] = 0.f;
}

// CSR fill (real edges; padding already written by k_scan23).
// Order of edges within a 16-block is arbitrary — gather sums commutatively.
__global__ __launch_bounds__(256) void k_fill(const int* __restrict__ src,
                                              const int* __restrict__ dst) {
    int e = blockIdx.x * 256 + threadIdx.x;
    if (e < EE) {
        int slot = atomicAdd(&g_pos[dst[e]], 1);
        g_csr[slot] = src[e];
    }
}

// ---------------------------------------------------------------------------
// Helper: write fp32 acc[DD] row to g_p and fp16 copy to g_ph
__device__ __forceinline__ void write_row(int node, const float* acc) {
    float4* pp = (float4*)&g_p[(size_t)node * DD];
#pragma unroll
    for (int j4 = 0; j4 < 8; j4++)
        pp[j4] = make_float4(acc[j4 * 4], acc[j4 * 4 + 1], acc[j4 * 4 + 2], acc[j4 * 4 + 3]);
    __half2 hb[DD / 2];
#pragma unroll
    for (int j = 0; j < DD / 2; j++)
        hb[j] = __floats2half2_rn(acc[2 * j], acc[2 * j + 1]);
    uint4* hp = (uint4*)&g_ph[(size_t)node * DD];
    const uint4* hs = (const uint4*)hb;
#pragma unroll
    for (int j = 0; j < 4; j++) hp[j] = hs[j];
}

// Layer-1 projection: p = x @ W1a  (N x 128 @ 128 x 32)
__global__ __launch_bounds__(256) void k_proj1(const float* __restrict__ x,
                                               const float* __restrict__ W) {
    __shared__ __align__(16) float sW[FI * DD];
    for (int i = threadIdx.x; i < FI * DD; i += 256) sW[i] = W[i];
    __syncthreads();

    int node = blockIdx.x * 256 + threadIdx.x;
    if (node >= NN) return;

    float acc[DD];
#pragma unroll
    for (int j = 0; j < DD; j++) acc[j] = 0.f;

    const float4* xr = (const float4*)(x + (size_t)node * FI);
#pragma unroll 4
    for (int k4 = 0; k4 < FI / 4; k4++) {
        float4 xv = xr[k4];
#pragma unroll
        for (int t = 0; t < 4; t++) {
            float xs = (t == 0) ? xv.x : (t == 1) ? xv.y : (t == 2) ? xv.z : xv.w;
            const float4* wr = (const float4*)&sW[(k4 * 4 + t) * DD];
#pragma unroll
            for (int j4 = 0; j4 < DD / 4; j4++) {
                float4 w = wr[j4];
                acc[j4 * 4 + 0] += xs * w.x;
                acc[j4 * 4 + 1] += xs * w.y;
                acc[j4 * 4 + 2] += xs * w.z;
                acc[j4 * 4 + 3] += xs * w.w;
            }
        }
    }
    write_row(node, acc);
}

// ---------------------------------------------------------------------------
// Layers 2-5 projection with folded BatchNorm:
//   bn(h) = s*h + c;  p = h @ (diag(s)Wa) + c@Wa
__global__ __launch_bounds__(256) void k_proj(int stats_layer,
                                              const float* __restrict__ gamma,
                                              const float* __restrict__ beta,
                                              const float* __restrict__ Wa) {
    __shared__ float sS[DD], sC[DD], sCB[DD];
    __shared__ __align__(16) float sW[DD * DD];
    const float* st = g_stats + stats_layer * 2 * DD;
    if (threadIdx.x < DD) {
        float m = st[threadIdx.x] * (1.f / NN);
        float v = st[DD + threadIdx.x] * (1.f / NN) - m * m;
        float s = gamma[threadIdx.x] * rsqrtf(v + BN_EPS);
        sS[threadIdx.x] = s;
        sC[threadIdx.x] = beta[threadIdx.x] - m * s;
    }
    __syncthreads();
    for (int i = threadIdx.x; i < DD * DD; i += 256) sW[i] = sS[i >> 5] * Wa[i];
    __syncthreads();
    if (threadIdx.x < DD) {
        float c = 0.f;
#pragma unroll
        for (int f = 0; f < DD; f++) c += sC[f] * Wa[f * DD + threadIdx.x];
        sCB[threadIdx.x] = c;
    }
    __syncthreads();

    int node = blockIdx.x * 256 + threadIdx.x;
    if (node >= NN) return;

    float hv[DD];
    const float4* hr = (const float4*)&g_h[(size_t)node * DD];
#pragma unroll
    for (int j4 = 0; j4 < 8; j4++) {
        float4 t = hr[j4];
        hv[j4 * 4 + 0] = t.x; hv[j4 * 4 + 1] = t.y;
        hv[j4 * 4 + 2] = t.z; hv[j4 * 4 + 3] = t.w;
    }
    float acc[DD];
#pragma unroll
    for (int j = 0; j < DD; j++) acc[j] = sCB[j];
#pragma unroll 4
    for (int k = 0; k < DD; k++) {
        float hk = hv[k];
        const float4* wr = (const float4*)&sW[k * DD];
#pragma unroll
        for (int j4 = 0; j4 < 8; j4++) {
            float4 w = wr[j4];
            acc[j4 * 4 + 0] += hk * w.x;
            acc[j4 * 4 + 1] += hk * w.y;
            acc[j4 * 4 + 2] += hk * w.z;
            acc[j4 * 4 + 3] += hk * w.w;
        }
    }
    write_row(node, acc);
}

// ---------------------------------------------------------------------------
// Fused gather + MLP + stats. One warp per node; sub = lane>>3, quad = lane&7.
// CSR rows padded to multiples of 16 (zero-row entries). Each lane reads its
// 4 indices with one int4 load, then gathers fp16 rows (64B/row, LDG.64/lane)
// and accumulates in fp32. Self term read exact from fp32 g_p.
__global__ __launch_bounds__(256) void k_gma(const float* __restrict__ ba,
                                             const float* __restrict__ Wb,
                                             const float* __restrict__ bb,
                                             int stats_layer) {
    __shared__ __align__(16) float sT[8][DD];
    __shared__ float sba4[DD], sS[DD], sQ[DD];
    int lane = threadIdx.x & 31;
    int w = threadIdx.x >> 5;

    float wb[DD];   // column `lane` of Wb
#pragma unroll
    for (int k = 0; k < DD; k++) wb[k] = Wb[k * DD + lane];
    float bbl = bb[lane];

    if (threadIdx.x < DD) {
        sba4[threadIdx.x] = ba[threadIdx.x];
        sS[threadIdx.x] = 0.f;
        sQ[threadIdx.x] = 0.f;
    }
    __syncthreads();

    int sub = lane >> 3;
    int quad = lane & 7;
    const unsigned FULL = 0xffffffffu;

    int warpsTotal = gridDim.x * 8;
    float ls = 0.f, lq = 0.f;

    for (int n = blockIdx.x * 8 + w; n < NN; n += warpsTotal) {
        int2 rd = g_rd[n];
        int base = rd.x, cnt = rd.y;   // cnt is a multiple of 16
        float4 a4 = make_float4(0.f, 0.f, 0.f, 0.f);
        for (int i = 0; i < cnt; i += 16) {
            int4 ss = *(const int4*)&g_csr[base + i + sub * 4];
            uint2 u0 = *(const uint2*)&g_ph[(size_t)ss.x * DD + quad * 4];
            uint2 u1 = *(const uint2*)&g_ph[(size_t)ss.y * DD + quad * 4];
            uint2 u2 = *(const uint2*)&g_ph[(size_t)ss.z * DD + quad * 4];
            uint2 u3 = *(const uint2*)&g_ph[(size_t)ss.w * DD + quad * 4];
            float2 f0a = __half22float2(*(const __half2*)&u0.x);
            float2 f0b = __half22float2(*(const __half2*)&u0.y);
            float2 f1a = __half22float2(*(const __half2*)&u1.x);
            float2 f1b = __half22float2(*(const __half2*)&u1.y);
            float2 f2a = __half22float2(*(const __half2*)&u2.x);
            float2 f2b = __half22float2(*(const __half2*)&u2.y);
            float2 f3a = __half22float2(*(const __half2*)&u3.x);
            float2 f3b = __half22float2(*(const __half2*)&u3.y);
            a4.x += (f0a.x + f1a.x) + (f2a.x + f3a.x);
            a4.y += (f0a.y + f1a.y) + (f2a.y + f3a.y);
            a4.z += (f0b.x + f1b.x) + (f2b.x + f3b.x);
            a4.w += (f0b.y + f1b.y) + (f2b.y + f3b.y);
        }
        // reduce across the 4 edge subgroups
        a4.x += __shfl_xor_sync(FULL, a4.x, 8);
        a4.y += __shfl_xor_sync(FULL, a4.y, 8);
        a4.z += __shfl_xor_sync(FULL, a4.z, 8);
        a4.w += __shfl_xor_sync(FULL, a4.w, 8);
        a4.x += __shfl_xor_sync(FULL, a4.x, 16);
        a4.y += __shfl_xor_sync(FULL, a4.y, 16);
        a4.z += __shfl_xor_sync(FULL, a4.z, 16);
        a4.w += __shfl_xor_sync(FULL, a4.w, 16);

        // self term + bias + relu (exact fp32)
        float4 self = *(const float4*)&g_p[(size_t)n * DD + quad * 4];
        const float4 b4 = *(const float4*)&sba4[quad * 4];
        float4 t4;
        t4.x = fmaxf(a4.x + self.x + b4.x, 0.f);
        t4.y = fmaxf(a4.y + self.y + b4.y, 0.f);
        t4.z = fmaxf(a4.z + self.z + b4.z, 0.f);
        t4.w = fmaxf(a4.w + self.w + b4.w, 0.f);

        __syncwarp();
        if (lane < 8) *(float4*)&sT[w][lane * 4] = t4;
        __syncwarp();

        float hv = bbl;
#pragma unroll
        for (int k4 = 0; k4 < 8; k4++) {
            float4 tv = *(const float4*)&sT[w][k4 * 4];
            hv = fmaf(tv.x, wb[k4 * 4 + 0], hv);
            hv = fmaf(tv.y, wb[k4 * 4 + 1], hv);
            hv = fmaf(tv.z, wb[k4 * 4 + 2], hv);
            hv = fmaf(tv.w, wb[k4 * 4 + 3], hv);
        }
        hv = fmaxf(hv, 0.f);
        g_h[(size_t)n * DD + lane] = hv;
        ls += hv;
        lq += hv * hv;
    }

    atomicAdd(&sS[lane], ls);
    atomicAdd(&sQ[lane], lq);
    __syncthreads();
    if (w == 0) {
        float* st = g_stats + stats_layer * 2 * DD;
        atomicAdd(&st[lane], sS[lane]);
        atomicAdd(&st[DD + lane], sQ[lane]);
    }
}

// ---------------------------------------------------------------------------
// Segmented global add pool (batch is sorted)
__global__ __launch_bounds__(256) void k_pool(const int* __restrict__ batch,
                                              const float* __restrict__ gamma,
                                              const float* __restrict__ beta) {
    __shared__ float sS[DD], sC[DD];
    const float* st = g_stats + 4 * 2 * DD;
    if (threadIdx.x < DD) {
        float m = st[threadIdx.x] * (1.f / NN);
        float v = st[DD + threadIdx.x] * (1.f / NN) - m * m;
        float s = gamma[threadIdx.x] * rsqrtf(v + BN_EPS);
        sS[threadIdx.x] = s;
        sC[threadIdx.x] = beta[threadIdx.x] - m * s;
    }
    __syncthreads();

    int lane = threadIdx.x & 31;
    int w = threadIdx.x >> 5;
    int wid = blockIdx.x * 8 + w;
    int n0 = wid * 64;
    if (n0 >= NN) return;
    int n1 = min(n0 + 64, NN);

    float s = sS[lane], c = sC[lane];
    int curg = __ldg(&batch[n0]);
    float acc = 0.f;
    for (int n = n0; n < n1; n++) {
        int g = __ldg(&batch[n]);
        if (g != curg) {
            atomicAdd(&g_pooled[curg * DD + lane], acc);
            acc = 0.f;
            curg = g;
        }
        acc = fmaf(s, g_h[(size_t)n * DD + lane], acc + c);
    }
    atomicAdd(&g_pooled[curg * DD + lane], acc);
}

// ---------------------------------------------------------------------------
// Head: relu(pooled@fc1+b1) @ fc2 + b2, log_softmax. One thread per graph.
__global__ __launch_bounds__(256) void k_head(const float* __restrict__ fc1w,
                                              const float* __restrict__ fc1b,
                                              const float* __restrict__ fc2w,
                                              const float* __restrict__ fc2b,
                                              float* __restrict__ out) {
    __shared__ float sW1[DD * DD], sW2[DD * CC], sb1[DD], sb2[CC];
    for (int i = threadIdx.x; i < DD * DD; i += 256) sW1[i] = fc1w[i];
    for (int i = threadIdx.x; i < DD * CC; i += 256) sW2[i] = fc2w[i];
    if (threadIdx.x < DD) sb1[threadIdx.x] = fc1b[threadIdx.x];
    if (threadIdx.x < CC) sb2[threadIdx.x] = fc2b[threadIdx.x];
    __syncthreads();

    int g = blockIdx.x * 256 + threadIdx.x;
    if (g >= GG) return;

    float pv[DD];
    const float4* pr = (const float4*)&g_pooled[g * DD];
#pragma unroll
    for (int j4 = 0; j4 < 8; j4++) {
        float4 t = pr[j4];
        pv[j4 * 4 + 0] = t.x; pv[j4 * 4 + 1] = t.y;
        pv[j4 * 4 + 2] = t.z; pv[j4 * 4 + 3] = t.w;
    }
    float u[DD];
#pragma unroll
    for (int j = 0; j < DD; j++) u[j] = sb1[j];
#pragma unroll 4
    for (int k = 0; k < DD; k++) {
        float pk = pv[k];
#pragma unroll
        for (int j = 0; j < DD; j++) u[j] += pk * sW1[k * DD + j];
    }
#pragma unroll
    for (int j = 0; j < DD; j++) u[j] = fmaxf(u[j], 0.f);

    float lg[CC];
#pragma unroll
    for (int c = 0; c < CC; c++) lg[c] = sb2[c];
#pragma unroll 4
    for (int j = 0; j < DD; j++) {
        float uj = u[j];
#pragma unroll
        for (int c = 0; c < CC; c++) lg[c] += uj * sW2[j * CC + c];
    }
    float mx = lg[0];
#pragma unroll
    for (int c = 1; c < CC; c++) mx = fmaxf(mx, lg[c]);
    float se = 0.f;
#pragma unroll
    for (int c = 0; c < CC; c++) se += expf(lg[c] - mx);
    float lse = mx + logf(se);
#pragma unroll
    for (int c = 0; c < CC; c++) out[g * CC + c] = lg[c] - lse;
}

// ---------------------------------------------------------------------------
extern "C" void kernel_launch(void* const* d_in, const int* in_sizes, int n_in,
                              void* d_out, int out_size) {
    const float* x     = (const float*)d_in[0];
    const int*   ei    = (const int*)d_in[1];
    const int*   batch = (const int*)d_in[2];
    const float* W1a   = (const float*)d_in[3];
    const float* b1a   = (const float*)d_in[4];
    const float* W1b   = (const float*)d_in[5];
    const float* b1b   = (const float*)d_in[6];
    const float* Wa    = (const float*)d_in[7];
    const float* ba    = (const float*)d_in[8];
    const float* Wb    = (const float*)d_in[9];
    const float* bb    = (const float*)d_in[10];
    const float* gamma = (const float*)d_in[11];
    const float* beta  = (const float*)d_in[12];
    const float* fc1w  = (const float*)d_in[13];
    const float* fc1b  = (const float*)d_in[14];
    const float* fc2w  = (const float*)d_in[15];
    const float* fc2b  = (const float*)d_in[16];
    float* out = (float*)d_out;

    const int* src = ei;        // row 0
    const int* dst = ei + EE;   // row 1

    const int NB = (NN + 255) / 256;          // 391
    const int EB = EE / 256;                  // 6250
    const int SCAN_BLK = (NN + 1023) / 1024;  // 98
    const int GMA_BLK = 1480;
    const int PB = ((NN + 63) / 64 + 7) / 8;

    // CSR build (padded rows; g_deg zero by invariant)
    k_hist<<<EB, 256>>>(dst);
    k_scan1<<<SCAN_BLK, 256>>>();
    k_scan23<<<NB, 256>>>();
    k_fill<<<EB, 256>>>(src, dst);

    // Layer-1 projection
    k_proj1<<<NB, 256>>>(x, W1a);

    // Layer 1 gather+MLP+stats
    k_gma<<<GMA_BLK, 256>>>(b1a, W1b, b1b, 0);

    // Layers 2-5 (BN folded into projection)
    for (int i = 0; i < 4; i++) {
        k_proj<<<NB, 256>>>(i, gamma + i * DD, beta + i * DD, Wa + i * DD * DD);
        k_gma<<<GMA_BLK, 256>>>(ba + i * DD, Wb + i * DD * DD, bb + i * DD, i + 1);
    }

    // Pool (applies BN layer 5) + head
    k_pool<<<PB, 256>>>(batch, gamma + 4 * DD, beta + 4 * DD);
    k_head<<<(GG + 255) / 256, 256>>>(fc1w, fc1b, fc2w, fc2b, out);
}